// round 1
// baseline (speedup 1.0000x reference)
#include <cuda_runtime.h>

#define NUM_V 100000
#define NUM_R 1000
#define DV 192   // D+I
#define DR 128
#define H 128
#define B 4096
#define N 64
#define ARITY 3
#define ROWS_PER_CHUNK 8
#define NCHUNK (NUM_V / ROWS_PER_CHUNK)   // 12500

// Precomputed tables (scratch: __device__ globals per harness rules)
__device__ float g_VW[NUM_V * H];   // 51.2 MB — fits in L2 for the gather pass
__device__ float g_XR[NUM_R * H];   // 0.5 MB
__device__ float g_pp[H];           // prod_a (P[a]@WP + bP)

// ---------------------------------------------------------------------------
// Kernel 1: XR = R@WR + bR  (blocks 0..999), pp = prod_a(P@WP + bP) (block 1000)
// ---------------------------------------------------------------------------
__global__ void prep_kernel(const float* __restrict__ R, const float* __restrict__ WR,
                            const float* __restrict__ bR,
                            const float* __restrict__ P, const float* __restrict__ WP,
                            const float* __restrict__ bP) {
    __shared__ float srow[DR];
    __shared__ float sp[ARITY * DR];
    int h = threadIdx.x;
    int blk = blockIdx.x;
    if (blk < NUM_R) {
        srow[h] = R[blk * DR + h];
        __syncthreads();
        float acc = bR[h];
        #pragma unroll 8
        for (int d = 0; d < DR; d++) acc = fmaf(srow[d], WR[d * H + h], acc);
        g_XR[blk * H + h] = acc;
    } else {
        for (int i = h; i < ARITY * DR; i += H) sp[i] = P[i];
        __syncthreads();
        float prod = 1.0f;
        for (int a = 0; a < ARITY; a++) {
            float acc = bP[h];
            #pragma unroll 8
            for (int d = 0; d < DR; d++) acc = fmaf(sp[a * DR + d], WP[d * H + h], acc);
            prod *= acc;
        }
        g_pp[h] = prod;
    }
}

// ---------------------------------------------------------------------------
// Kernel 2: VW = V@WV + bV  (100000x192 @ 192x128), fp32 FFMA.
// W resident in shared (96 KB). 8 rows per thread per chunk so the FFMA pipe
// (32 FFMA per 12 LDS per 4-d step) is the binding resource.
// ---------------------------------------------------------------------------
__global__ void __launch_bounds__(128, 2)
vproj_kernel(const float* __restrict__ V, const float* __restrict__ WV,
             const float* __restrict__ bV) {
    extern __shared__ float smem[];
    float* sW = smem;                // DV*H   = 24576 floats (96 KB)
    float* sV = smem + DV * H;       // 8*DV   = 1536 floats  (6 KB)
    int tid = threadIdx.x;           // column h

    // Load W once per block (coalesced float4)
    const float4* W4 = (const float4*)WV;
    float4* sW4 = (float4*)sW;
    for (int i = tid; i < DV * H / 4; i += 128) sW4[i] = W4[i];
    float bias = bV[tid];

    for (int chunk = blockIdx.x; chunk < NCHUNK; chunk += gridDim.x) {
        __syncthreads();  // previous compute done reading sV (and W ready on iter 0)
        // Stage 8 contiguous V rows (6 KB contiguous, coalesced float4)
        const float4* Vsrc = (const float4*)(V + (size_t)chunk * ROWS_PER_CHUNK * DV);
        float4* sV4 = (float4*)sV;
        #pragma unroll
        for (int i = tid; i < ROWS_PER_CHUNK * DV / 4; i += 128) sV4[i] = Vsrc[i];
        __syncthreads();

        float acc[ROWS_PER_CHUNK];
        #pragma unroll
        for (int k = 0; k < ROWS_PER_CHUNK; k++) acc[k] = bias;

        for (int d = 0; d < DV; d += 4) {
            float4 v4[ROWS_PER_CHUNK];
            #pragma unroll
            for (int k = 0; k < ROWS_PER_CHUNK; k++)
                v4[k] = *(const float4*)(sV + k * DV + d);
            #pragma unroll
            for (int dd = 0; dd < 4; dd++) {
                float w = sW[(d + dd) * H + tid];
                #pragma unroll
                for (int k = 0; k < ROWS_PER_CHUNK; k++) {
                    float v = (dd == 0) ? v4[k].x : (dd == 1) ? v4[k].y
                            : (dd == 2) ? v4[k].z : v4[k].w;
                    acc[k] = fmaf(v, w, acc[k]);
                }
            }
        }
        #pragma unroll
        for (int k = 0; k < ROWS_PER_CHUNK; k++)
            g_VW[(size_t)(chunk * ROWS_PER_CHUNK + k) * H + tid] = acc[k];
    }
}

// ---------------------------------------------------------------------------
// Kernel 3: out[b,h] = pp[h] * sum_n XR[r[b,n],h] * VW[e0]*VW[e1]*VW[e2]
// 512 MB of gathers, VW+XR tables L2-resident -> L2-BW bound.
// ---------------------------------------------------------------------------
__global__ void __launch_bounds__(128)
gather_kernel(const int* __restrict__ r, const int* __restrict__ e,
              float* __restrict__ out) {
    __shared__ int sidx[4 * N];
    int tid = threadIdx.x;
    int b = blockIdx.x;
    for (int i = tid; i < 4 * N; i += 128) {
        int k = i >> 6, n = i & 63;
        sidx[i] = (k == 0) ? r[b * N + n] : e[(k - 1) * (B * N) + b * N + n];
    }
    __syncthreads();
    float acc = 0.f;
    #pragma unroll 4
    for (int n = 0; n < N; n++) {
        int ir = sidx[n];
        int i0 = sidx[64 + n];
        int i1 = sidx[128 + n];
        int i2 = sidx[192 + n];
        float xr = g_XR[ir * H + tid];
        float v0 = g_VW[(size_t)i0 * H + tid];
        float v1 = g_VW[(size_t)i1 * H + tid];
        float v2 = g_VW[(size_t)i2 * H + tid];
        acc += xr * (v0 * (v1 * v2));
    }
    out[b * H + tid] = acc * g_pp[tid];
}

// ---------------------------------------------------------------------------
extern "C" void kernel_launch(void* const* d_in, const int* in_sizes, int n_in,
                              void* d_out, int out_size) {
    const int*   r  = (const int*)d_in[0];
    const int*   e  = (const int*)d_in[1];
    const float* V  = (const float*)d_in[2];
    const float* R  = (const float*)d_in[3];
    const float* P  = (const float*)d_in[4];
    const float* WV = (const float*)d_in[5];
    const float* bV = (const float*)d_in[6];
    const float* WR = (const float*)d_in[7];
    const float* bR = (const float*)d_in[8];
    const float* WP = (const float*)d_in[9];
    const float* bP = (const float*)d_in[10];
    float* out = (float*)d_out;

    int smem = (DV * H + ROWS_PER_CHUNK * DV) * (int)sizeof(float);  // 102 KB
    cudaFuncSetAttribute(vproj_kernel, cudaFuncAttributeMaxDynamicSharedMemorySize, smem);

    prep_kernel<<<NUM_R + 1, H>>>(R, WR, bR, P, WP, bP);
    vproj_kernel<<<296, 128, smem>>>(V, WV, bV);   // 2 blocks/SM x 148 SMs
    gather_kernel<<<B, H>>>(r, e, out);
}

// round 3
// speedup vs baseline: 2.3832x; 2.3832x over previous
#include <cuda_runtime.h>
#include <cuda_fp16.h>

#define NUM_V 100000
#define NUM_R 1000
#define DV 192   // D+I (K dim of V projection)
#define DR 128
#define H 128
#define B 4096
#define N 64
#define ARITY 3

#define VT_ROWS 32                 // V rows per tile
#define NTILES  (NUM_V / VT_ROWS)  // 3125 (exact)
#define KSTEPS  (DV / 16)          // 12
#define KK      (DV / 2)           // 96 half2 per row
#define KPAD    100                // padded stride in u32 (conflict-free)

__device__ __align__(16) float g_VW[NUM_V * H];   // 51.2 MB (L2-resident for gather)
__device__ __align__(16) float g_XR[NUM_R * H];
__device__ __align__(16) float g_pp[H];

// ---------------------------------------------------------------------------
// helpers
// ---------------------------------------------------------------------------
__device__ __forceinline__ void cvt_pair(float x, float y, unsigned& hi, unsigned& lo) {
    __half h0 = __float2half_rn(x); float r0 = x - __half2float(h0);
    __half h1 = __float2half_rn(y); float r1 = y - __half2float(h1);
    hi = (unsigned)__half_as_ushort(h0) | ((unsigned)__half_as_ushort(h1) << 16);
    lo = (unsigned)__half_as_ushort(__float2half_rn(r0))
       | ((unsigned)__half_as_ushort(__float2half_rn(r1)) << 16);
}

__device__ __forceinline__ void mma16816(float c[4],
                                         unsigned a0, unsigned a1, unsigned a2, unsigned a3,
                                         unsigned b0, unsigned b1) {
    asm volatile(
        "mma.sync.aligned.m16n8k16.row.col.f32.f16.f16.f32 "
        "{%0,%1,%2,%3},{%4,%5,%6,%7},{%8,%9},{%0,%1,%2,%3};\n"
        : "+f"(c[0]), "+f"(c[1]), "+f"(c[2]), "+f"(c[3])
        : "r"(a0), "r"(a1), "r"(a2), "r"(a3), "r"(b0), "r"(b1));
}

// ---------------------------------------------------------------------------
// Kernel 1: XR = R@WR + bR (blocks 0..124, 8 rows each); pp (block 125)
// ---------------------------------------------------------------------------
__global__ void __launch_bounds__(128)
prep_kernel(const float* __restrict__ R, const float* __restrict__ WR,
            const float* __restrict__ bR,
            const float* __restrict__ P, const float* __restrict__ WP,
            const float* __restrict__ bP) {
    int h = threadIdx.x;
    int blk = blockIdx.x;
    if (blk < 125) {
        __shared__ float sR[8 * DR];
        #pragma unroll
        for (int k = 0; k < 8; k++) sR[k * DR + h] = R[(size_t)(8 * blk + k) * DR + h];
        __syncthreads();
        float acc[8];
        float bias = bR[h];
        #pragma unroll
        for (int k = 0; k < 8; k++) acc[k] = bias;
        #pragma unroll 4
        for (int d = 0; d < DR; d++) {
            float w = WR[d * H + h];
            #pragma unroll
            for (int k = 0; k < 8; k++) acc[k] = fmaf(sR[k * DR + d], w, acc[k]);
        }
        #pragma unroll
        for (int k = 0; k < 8; k++) g_XR[(size_t)(8 * blk + k) * H + h] = acc[k];
    } else {
        __shared__ float sp[ARITY * DR];
        for (int i = h; i < ARITY * DR; i += H) sp[i] = P[i];
        __syncthreads();
        float prod = 1.0f;
        for (int a = 0; a < ARITY; a++) {
            float acc = bP[h];
            #pragma unroll 4
            for (int d = 0; d < DR; d++) acc = fmaf(sp[a * DR + d], WP[d * H + h], acc);
            prod *= acc;
        }
        g_pp[h] = prod;
    }
}

// ---------------------------------------------------------------------------
// Kernel 2: VW = V@WV + bV via tensor cores (f16 split: hi*hi + hi*lo + lo*hi)
// Persistent: 148 blocks x 256 threads. W resident in shared (hi/lo half2),
// V tiles (32 rows) double-buffered with register prefetch.
// Warp w: row-group rg=(w&1)*16, n-range nb=(w>>1)*32 (4 ntiles of 8 cols).
// ---------------------------------------------------------------------------
__global__ void __launch_bounds__(256, 1)
vproj_kernel(const float* __restrict__ V, const float* __restrict__ WV,
             const float* __restrict__ bV) {
    extern __shared__ unsigned smem_u[];
    unsigned* sWhi = smem_u;                 // 128*100
    unsigned* sWlo = smem_u + H * KPAD;      // 128*100
    unsigned* sV   = smem_u + 2 * H * KPAD;  // 2 bufs * (hi 3200 + lo 3200)

    int tid = threadIdx.x;
    int w = tid >> 5, lane = tid & 31;
    int g = lane >> 2, tg = lane & 3;
    int rg = (w & 1) * 16;
    int nb = (w >> 1) * 32;

    // --- one-time: split W into shared (hi/lo), layout [n][kk], stride KPAD ---
    for (int idx = tid; idx < KK * H; idx += 256) {
        int kk = idx >> 7, n = idx & 127;
        unsigned hi, lo;
        cvt_pair(WV[(2 * kk) * H + n], WV[(2 * kk + 1) * H + n], hi, lo);
        sWhi[n * KPAD + kk] = hi;
        sWlo[n * KPAD + kk] = lo;
    }

    // bias registers (per-warp columns)
    float bvx[4], bvy[4];
    #pragma unroll
    for (int nt = 0; nt < 4; nt++) {
        int col = nb + nt * 8 + 2 * tg;
        bvx[nt] = bV[col];
        bvy[nt] = bV[col + 1];
    }

    // --- prologue: load+convert first tile into buf 0 ---
    int t = blockIdx.x;
    if (t < NTILES) {
        unsigned* vh = sV;
        unsigned* vl = sV + VT_ROWS * KPAD;
        for (int j = 0; j < 12; j++) {
            int idx = tid + j * 256;           // 3072 = 12*256 exact
            int row = idx / KK, kk = idx - row * KK;
            float2 v = *(const float2*)(V + (size_t)(t * VT_ROWS + row) * DV + 2 * kk);
            unsigned hi, lo;
            cvt_pair(v.x, v.y, hi, lo);
            vh[row * KPAD + kk] = hi;
            vl[row * KPAD + kk] = lo;
        }
    }
    __syncthreads();

    int buf = 0;
    for (; t < NTILES; t += gridDim.x) {
        int tn = t + gridDim.x;
        // prefetch next tile into registers (LDGs overlap with MMA below)
        float2 pv[12];
        if (tn < NTILES) {
            #pragma unroll
            for (int j = 0; j < 12; j++) {
                int idx = tid + j * 256;
                int row = idx / KK, kk = idx - row * KK;
                pv[j] = *(const float2*)(V + (size_t)(tn * VT_ROWS + row) * DV + 2 * kk);
            }
        }

        // --- compute on current buffer ---
        unsigned* vh = sV + buf * (2 * VT_ROWS * KPAD);
        unsigned* vl = vh + VT_ROWS * KPAD;
        float c[4][4];
        #pragma unroll
        for (int nt = 0; nt < 4; nt++)
            #pragma unroll
            for (int i = 0; i < 4; i++) c[nt][i] = 0.f;

        int rowA = rg + g;
        #pragma unroll
        for (int ks = 0; ks < KSTEPS; ks++) {
            int kb = ks * 8 + tg;
            unsigned ah0 = vh[rowA * KPAD + kb];
            unsigned ah1 = vh[(rowA + 8) * KPAD + kb];
            unsigned ah2 = vh[rowA * KPAD + kb + 4];
            unsigned ah3 = vh[(rowA + 8) * KPAD + kb + 4];
            unsigned al0 = vl[rowA * KPAD + kb];
            unsigned al1 = vl[(rowA + 8) * KPAD + kb];
            unsigned al2 = vl[rowA * KPAD + kb + 4];
            unsigned al3 = vl[(rowA + 8) * KPAD + kb + 4];
            #pragma unroll
            for (int nt = 0; nt < 4; nt++) {
                int nc = nb + nt * 8 + g;
                unsigned bh0 = sWhi[nc * KPAD + kb];
                unsigned bh1 = sWhi[nc * KPAD + kb + 4];
                unsigned bl0 = sWlo[nc * KPAD + kb];
                unsigned bl1 = sWlo[nc * KPAD + kb + 4];
                mma16816(c[nt], ah0, ah1, ah2, ah3, bh0, bh1);
                mma16816(c[nt], ah0, ah1, ah2, ah3, bl0, bl1);
                mma16816(c[nt], al0, al1, al2, al3, bh0, bh1);
            }
        }

        // --- epilogue: store tile results (+bias) ---
        {
            int grow = t * VT_ROWS + rg + g;
            #pragma unroll
            for (int nt = 0; nt < 4; nt++) {
                int col = nb + nt * 8 + 2 * tg;
                float2 r0 = make_float2(c[nt][0] + bvx[nt], c[nt][1] + bvy[nt]);
                float2 r1 = make_float2(c[nt][2] + bvx[nt], c[nt][3] + bvy[nt]);
                *(float2*)(g_VW + (size_t)grow * H + col) = r0;
                *(float2*)(g_VW + (size_t)(grow + 8) * H + col) = r1;
            }
        }

        // --- convert+store prefetched tile into other buffer ---
        if (tn < NTILES) {
            unsigned* nvh = sV + (buf ^ 1) * (2 * VT_ROWS * KPAD);
            unsigned* nvl = nvh + VT_ROWS * KPAD;
            #pragma unroll
            for (int j = 0; j < 12; j++) {
                int idx = tid + j * 256;
                int row = idx / KK, kk = idx - row * KK;
                unsigned hi, lo;
                cvt_pair(pv[j].x, pv[j].y, hi, lo);
                nvh[row * KPAD + kk] = hi;
                nvl[row * KPAD + kk] = lo;
            }
        }
        __syncthreads();
        buf ^= 1;
    }
}

// ---------------------------------------------------------------------------
// Kernel 3: out[b,h] = pp[h] * sum_n XR[r[b,n],h] * VW[e0]*VW[e1]*VW[e2]
// float4 lanes: warp covers full 128-col row per LDG.128; 4 warps split n.
// ---------------------------------------------------------------------------
__global__ void __launch_bounds__(128)
gather_kernel(const int* __restrict__ r, const int* __restrict__ e,
              float* __restrict__ out) {
    __shared__ int sidx[4 * N];
    __shared__ float4 sacc[128];
    int tid = threadIdx.x;
    int w = tid >> 5, l = tid & 31;
    int b = blockIdx.x;
    for (int i = tid; i < 4 * N; i += 128) {
        int k = i >> 6, n = i & 63;
        sidx[i] = (k == 0) ? r[b * N + n] : e[(k - 1) * (B * N) + b * N + n];
    }
    __syncthreads();

    const float4* XR4 = (const float4*)g_XR;
    const float4* VW4 = (const float4*)g_VW;
    float4 acc = make_float4(0.f, 0.f, 0.f, 0.f);
    #pragma unroll 4
    for (int i = 0; i < 16; i++) {
        int n = w + i * 4;
        int ir = sidx[n];
        int i0 = sidx[64 + n];
        int i1 = sidx[128 + n];
        int i2 = sidx[192 + n];
        float4 xr = XR4[ir * 32 + l];
        float4 v0 = VW4[i0 * 32 + l];
        float4 v1 = VW4[i1 * 32 + l];
        float4 v2 = VW4[i2 * 32 + l];
        acc.x += xr.x * (v0.x * (v1.x * v2.x));
        acc.y += xr.y * (v0.y * (v1.y * v2.y));
        acc.z += xr.z * (v0.z * (v1.z * v2.z));
        acc.w += xr.w * (v0.w * (v1.w * v2.w));
    }
    sacc[tid] = acc;
    __syncthreads();
    if (w == 0) {
        float4 a0 = sacc[l], a1 = sacc[32 + l], a2 = sacc[64 + l], a3 = sacc[96 + l];
        float4 pp = ((const float4*)g_pp)[l];
        float4 o;
        o.x = (a0.x + a1.x + a2.x + a3.x) * pp.x;
        o.y = (a0.y + a1.y + a2.y + a3.y) * pp.y;
        o.z = (a0.z + a1.z + a2.z + a3.z) * pp.z;
        o.w = (a0.w + a1.w + a2.w + a3.w) * pp.w;
        ((float4*)out)[b * 32 + l] = o;
    }
}

// ---------------------------------------------------------------------------
extern "C" void kernel_launch(void* const* d_in, const int* in_sizes, int n_in,
                              void* d_out, int out_size) {
    const int*   r  = (const int*)d_in[0];
    const int*   e  = (const int*)d_in[1];
    const float* V  = (const float*)d_in[2];
    const float* R  = (const float*)d_in[3];
    const float* P  = (const float*)d_in[4];
    const float* WV = (const float*)d_in[5];
    const float* bV = (const float*)d_in[6];
    const float* WR = (const float*)d_in[7];
    const float* bR = (const float*)d_in[8];
    const float* WP = (const float*)d_in[9];
    const float* bP = (const float*)d_in[10];
    float* out = (float*)d_out;

    int smem = (2 * H * KPAD + 2 * 2 * VT_ROWS * KPAD) * (int)sizeof(unsigned); // 153.6 KB
    cudaFuncSetAttribute(vproj_kernel, cudaFuncAttributeMaxDynamicSharedMemorySize, smem);

    prep_kernel<<<126, 128>>>(R, WR, bR, P, WP, bP);
    vproj_kernel<<<148, 256, smem>>>(V, WV, bV);
    gather_kernel<<<B, 128>>>(r, e, out);
}

// round 4
// speedup vs baseline: 2.4243x; 1.0172x over previous
#include <cuda_runtime.h>
#include <cuda_fp16.h>

#define NUM_V 100000
#define NUM_R 1000
#define DV 192   // D+I (K dim of V projection)
#define DR 128
#define H 128
#define B 4096
#define N 64
#define ARITY 3

#define VT_ROWS 32                 // V rows per tile
#define NTILES  (NUM_V / VT_ROWS)  // 3125 (exact)
#define KSTEPS  (DV / 16)          // 12
#define KK      (DV / 2)           // 96 half2 per row
#define RS      52                 // row stride in uint4 (52%8==4 -> conflict-free LDS.128)

__device__ __align__(16) float g_VW[NUM_V * H];   // 51.2 MB (L2-resident for gather)
__device__ __align__(16) float g_XR[NUM_R * H];
__device__ __align__(16) float g_pp[H];

// ---------------------------------------------------------------------------
// helpers
// ---------------------------------------------------------------------------
__device__ __forceinline__ void cvt_pair(float x, float y, unsigned& hi, unsigned& lo) {
    __half h0 = __float2half_rn(x); float r0 = x - __half2float(h0);
    __half h1 = __float2half_rn(y); float r1 = y - __half2float(h1);
    hi = (unsigned)__half_as_ushort(h0) | ((unsigned)__half_as_ushort(h1) << 16);
    lo = (unsigned)__half_as_ushort(__float2half_rn(r0))
       | ((unsigned)__half_as_ushort(__float2half_rn(r1)) << 16);
}

__device__ __forceinline__ void mma16816(float c[4],
                                         unsigned a0, unsigned a1, unsigned a2, unsigned a3,
                                         unsigned b0, unsigned b1) {
    asm volatile(
        "mma.sync.aligned.m16n8k16.row.col.f32.f16.f16.f32 "
        "{%0,%1,%2,%3},{%4,%5,%6,%7},{%8,%9},{%0,%1,%2,%3};\n"
        : "+f"(c[0]), "+f"(c[1]), "+f"(c[2]), "+f"(c[3])
        : "r"(a0), "r"(a1), "r"(a2), "r"(a3), "r"(b0), "r"(b1));
}

// ---------------------------------------------------------------------------
// Kernel: prep (fused) + VW = V@WV + bV via tensor cores
// f16 split: hi*hi + hi*lo + lo*hi.  Persistent 148 blocks x 256 threads.
// Shared layout (uint4 elements, row stride RS=52):
//   sB[n][ks*4+tg]  = {Whi(kb), Whi(kb+4), Wlo(kb), Wlo(kb+4)}, kb=ks*8+tg
//   sA[row][ks*4+tg] same for V rows (double-buffered).
// Inner loop: 6 LDS.128 per 12 HMMA.
// ---------------------------------------------------------------------------
__global__ void __launch_bounds__(256, 1)
vproj_kernel(const float* __restrict__ V, const float* __restrict__ WV,
             const float* __restrict__ bV,
             const float* __restrict__ R, const float* __restrict__ WR,
             const float* __restrict__ bR,
             const float* __restrict__ P, const float* __restrict__ WP,
             const float* __restrict__ bP) {
    extern __shared__ uint4 smem4[];
    uint4* sB = smem4;                    // 128*52 = 6656 uint4
    uint4* sA = smem4 + H * RS;           // 2 bufs * 32*52
    unsigned* sBu = (unsigned*)sB;
    unsigned* sAu = (unsigned*)sA;

    __shared__ float sR[8 * DR];          // prep staging (also holds P: 384 <= 1024)

    int tid = threadIdx.x;
    int w = tid >> 5, lane = tid & 31;
    int g = lane >> 2, tg = lane & 3;
    int rg = (w & 1) * 16;
    int nb = (w >> 1) * 32;
    int blk = blockIdx.x;

    // ---------------- fused prep: XR (blocks 0..124), pp (block 125) --------
    if (blk < 125) {
        int h = tid & 127;
        if (tid < 128) {
            #pragma unroll
            for (int k = 0; k < 8; k++) sR[k * DR + h] = R[(size_t)(8 * blk + k) * DR + h];
        }
        __syncthreads();
        if (tid < 128) {
            float acc[8];
            float bias = bR[h];
            #pragma unroll
            for (int k = 0; k < 8; k++) acc[k] = bias;
            #pragma unroll 4
            for (int d = 0; d < DR; d++) {
                float wv = WR[d * H + h];
                #pragma unroll
                for (int k = 0; k < 8; k++) acc[k] = fmaf(sR[k * DR + d], wv, acc[k]);
            }
            #pragma unroll
            for (int k = 0; k < 8; k++) g_XR[(size_t)(8 * blk + k) * H + h] = acc[k];
        }
        __syncthreads();
    } else if (blk == 125) {
        int h = tid & 127;
        if (tid < 128) {
            for (int i = h; i < ARITY * DR; i += 128) sR[i] = P[i];
        }
        __syncthreads();
        if (tid < 128) {
            float prod = 1.0f;
            for (int a = 0; a < ARITY; a++) {
                float acc = bP[h];
                #pragma unroll 4
                for (int d = 0; d < DR; d++) acc = fmaf(sR[a * DR + d], WP[d * H + h], acc);
                prod *= acc;
            }
            g_pp[h] = prod;
        }
        __syncthreads();
    }

    // ---------------- one-time: split W into shared -------------------------
    for (int idx = tid; idx < KK * H; idx += 256) {
        int kk = idx >> 7, n = idx & 127;
        unsigned hi, lo;
        cvt_pair(WV[(2 * kk) * H + n], WV[(2 * kk + 1) * H + n], hi, lo);
        int wd = (n * RS + (kk >> 3) * 4 + (kk & 3)) * 4 + ((kk >> 2) & 1);
        sBu[wd] = hi;
        sBu[wd + 2] = lo;
    }

    // bias registers (per-warp columns)
    float bvx[4], bvy[4];
    #pragma unroll
    for (int nt = 0; nt < 4; nt++) {
        int col = nb + nt * 8 + 2 * tg;
        bvx[nt] = bV[col];
        bvy[nt] = bV[col + 1];
    }

    // ---------------- prologue: convert first tile into buf 0 ---------------
    int t = blk;
    if (t < NTILES) {
        unsigned* dst = sAu;
        for (int j = 0; j < 12; j++) {
            int idx = tid + j * 256;           // 3072 = 12*256 exact
            int row = idx / KK, kk = idx - row * KK;
            float2 v = *(const float2*)(V + (size_t)(t * VT_ROWS + row) * DV + 2 * kk);
            unsigned hi, lo;
            cvt_pair(v.x, v.y, hi, lo);
            int wd = (row * RS + (kk >> 3) * 4 + (kk & 3)) * 4 + ((kk >> 2) & 1);
            dst[wd] = hi;
            dst[wd + 2] = lo;
        }
    }
    __syncthreads();

    int buf = 0;
    for (; t < NTILES; t += gridDim.x) {
        int tn = t + gridDim.x;
        // prefetch next tile into registers (LDGs overlap with MMA below)
        float2 pv[12];
        if (tn < NTILES) {
            #pragma unroll
            for (int j = 0; j < 12; j++) {
                int idx = tid + j * 256;
                int row = idx / KK, kk = idx - row * KK;
                pv[j] = *(const float2*)(V + (size_t)(tn * VT_ROWS + row) * DV + 2 * kk);
            }
        }

        // --- compute on current buffer ---
        const uint4* A = sA + buf * (VT_ROWS * RS);
        float c[4][4];
        #pragma unroll
        for (int nt = 0; nt < 4; nt++)
            #pragma unroll
            for (int i = 0; i < 4; i++) c[nt][i] = 0.f;

        int rowA = rg + g;
        #pragma unroll
        for (int ks = 0; ks < KSTEPS; ks++) {
            uint4 A0 = A[rowA * RS + ks * 4 + tg];         // {ah0, ah2, al0, al2}
            uint4 A1 = A[(rowA + 8) * RS + ks * 4 + tg];   // {ah1, ah3, al1, al3}
            #pragma unroll
            for (int nt = 0; nt < 4; nt++) {
                int nc = nb + nt * 8 + g;
                uint4 Bv = sB[nc * RS + ks * 4 + tg];      // {bh0, bh1, bl0, bl1}
                mma16816(c[nt], A0.x, A1.x, A0.y, A1.y, Bv.x, Bv.y);  // hi*hi
                mma16816(c[nt], A0.x, A1.x, A0.y, A1.y, Bv.z, Bv.w);  // hi*lo
                mma16816(c[nt], A0.z, A1.z, A0.w, A1.w, Bv.x, Bv.y);  // lo*hi
            }
        }

        // --- epilogue: store tile results (+bias) ---
        {
            int grow = t * VT_ROWS + rg + g;
            #pragma unroll
            for (int nt = 0; nt < 4; nt++) {
                int col = nb + nt * 8 + 2 * tg;
                float2 r0 = make_float2(c[nt][0] + bvx[nt], c[nt][1] + bvy[nt]);
                float2 r1 = make_float2(c[nt][2] + bvx[nt], c[nt][3] + bvy[nt]);
                *(float2*)(g_VW + (size_t)grow * H + col) = r0;
                *(float2*)(g_VW + (size_t)(grow + 8) * H + col) = r1;
            }
        }

        // --- convert prefetched tile into other buffer ---
        if (tn < NTILES) {
            unsigned* dst = sAu + (buf ^ 1) * (VT_ROWS * RS * 4);
            #pragma unroll
            for (int j = 0; j < 12; j++) {
                int idx = tid + j * 256;
                int row = idx / KK, kk = idx - row * KK;
                unsigned hi, lo;
                cvt_pair(pv[j].x, pv[j].y, hi, lo);
                int wd = (row * RS + (kk >> 3) * 4 + (kk & 3)) * 4 + ((kk >> 2) & 1);
                dst[wd] = hi;
                dst[wd + 2] = lo;
            }
        }
        __syncthreads();
        buf ^= 1;
    }
}

// ---------------------------------------------------------------------------
// Kernel: out[b,h] = pp[h] * sum_n XR[r[b,n],h] * VW[e0]*VW[e1]*VW[e2]
// float4 lanes: warp covers full 128-col row per LDG.128; 4 warps split n.
// ---------------------------------------------------------------------------
__global__ void __launch_bounds__(128)
gather_kernel(const int* __restrict__ r, const int* __restrict__ e,
              float* __restrict__ out) {
    __shared__ int sidx[4 * N];
    __shared__ float4 sacc[128];
    int tid = threadIdx.x;
    int w = tid >> 5, l = tid & 31;
    int b = blockIdx.x;
    for (int i = tid; i < 4 * N; i += 128) {
        int k = i >> 6, n = i & 63;
        sidx[i] = (k == 0) ? r[b * N + n] : e[(k - 1) * (B * N) + b * N + n];
    }
    __syncthreads();

    const float4* XR4 = (const float4*)g_XR;
    const float4* VW4 = (const float4*)g_VW;
    float4 acc = make_float4(0.f, 0.f, 0.f, 0.f);
    #pragma unroll 4
    for (int i = 0; i < 16; i++) {
        int n = w + i * 4;
        int ir = sidx[n];
        int i0 = sidx[64 + n];
        int i1 = sidx[128 + n];
        int i2 = sidx[192 + n];
        float4 xr = XR4[ir * 32 + l];
        float4 v0 = VW4[i0 * 32 + l];
        float4 v1 = VW4[i1 * 32 + l];
        float4 v2 = VW4[i2 * 32 + l];
        acc.x += xr.x * (v0.x * (v1.x * v2.x));
        acc.y += xr.y * (v0.y * (v1.y * v2.y));
        acc.z += xr.z * (v0.z * (v1.z * v2.z));
        acc.w += xr.w * (v0.w * (v1.w * v2.w));
    }
    sacc[tid] = acc;
    __syncthreads();
    if (w == 0) {
        float4 a0 = sacc[l], a1 = sacc[32 + l], a2 = sacc[64 + l], a3 = sacc[96 + l];
        float4 pp = ((const float4*)g_pp)[l];
        float4 o;
        o.x = (a0.x + a1.x + a2.x + a3.x) * pp.x;
        o.y = (a0.y + a1.y + a2.y + a3.y) * pp.y;
        o.z = (a0.z + a1.z + a2.z + a3.z) * pp.z;
        o.w = (a0.w + a1.w + a2.w + a3.w) * pp.w;
        ((float4*)out)[b * 32 + l] = o;
    }
}

// ---------------------------------------------------------------------------
extern "C" void kernel_launch(void* const* d_in, const int* in_sizes, int n_in,
                              void* d_out, int out_size) {
    const int*   r  = (const int*)d_in[0];
    const int*   e  = (const int*)d_in[1];
    const float* V  = (const float*)d_in[2];
    const float* R  = (const float*)d_in[3];
    const float* P  = (const float*)d_in[4];
    const float* WV = (const float*)d_in[5];
    const float* bV = (const float*)d_in[6];
    const float* WR = (const float*)d_in[7];
    const float* bR = (const float*)d_in[8];
    const float* WP = (const float*)d_in[9];
    const float* bP = (const float*)d_in[10];
    float* out = (float*)d_out;

    int smem = (H * RS + 2 * VT_ROWS * RS) * (int)sizeof(uint4);  // 159744 B
    cudaFuncSetAttribute(vproj_kernel, cudaFuncAttributeMaxDynamicSharedMemorySize, smem);

    vproj_kernel<<<148, 256, smem>>>(V, WV, bV, R, WR, bR, P, WP, bP);
    gather_kernel<<<B, 128>>>(r, e, out);
}

// round 5
// speedup vs baseline: 2.5421x; 1.0486x over previous
#include <cuda_runtime.h>
#include <cuda_fp16.h>

#define NUM_V 100000
#define NUM_R 1000
#define DV 192   // D+I (K dim of V projection)
#define DR 128
#define H 128
#define B 4096
#define N 64
#define ARITY 3

#define VT_ROWS 32                 // V rows per tile
#define NTILES  (NUM_V / VT_ROWS)  // 3125 (exact)
#define KSTEPS  (DV / 16)          // 12
#define KK      (DV / 2)           // 96 bf16x2 per row
#define RS      52                 // row stride in uint4 (52%8==4 -> conflict-free LDS.128)

__device__ __align__(16) float g_VW[NUM_V * H];   // 51.2 MB (L2-resident for gather)
__device__ __align__(16) float g_XR[NUM_R * H];
__device__ __align__(16) float g_pp[H];

// ---------------------------------------------------------------------------
// helpers
// ---------------------------------------------------------------------------
// Truncated-bf16 2-term split of a float pair:
//   hi = top 16 bits (exact truncation, packed via PRMT)
//   lo = RN-bf16 of (x - hi)  (subtract is exact; lo captures all dropped bits)
// Cost per 2 elems: 1 PRMT + 2 LOP3 (alu) + 2 FADD + 1 CVT (fma) = 3+3 balanced.
__device__ __forceinline__ void split_pair(float x, float y, unsigned& hi, unsigned& lo) {
    unsigned xb = __float_as_uint(x), yb = __float_as_uint(y);
    hi = __byte_perm(xb, yb, 0x7632);                     // {bf16(x), bf16(y)} truncated
    float lx = x - __uint_as_float(xb & 0xFFFF0000u);
    float ly = y - __uint_as_float(yb & 0xFFFF0000u);
    asm("cvt.rn.bf16x2.f32 %0, %1, %2;" : "=r"(lo) : "f"(ly), "f"(lx));
}

__device__ __forceinline__ void mma16816bf(float c[4],
                                           unsigned a0, unsigned a1, unsigned a2, unsigned a3,
                                           unsigned b0, unsigned b1) {
    asm volatile(
        "mma.sync.aligned.m16n8k16.row.col.f32.bf16.bf16.f32 "
        "{%0,%1,%2,%3},{%4,%5,%6,%7},{%8,%9},{%0,%1,%2,%3};\n"
        : "+f"(c[0]), "+f"(c[1]), "+f"(c[2]), "+f"(c[3])
        : "r"(a0), "r"(a1), "r"(a2), "r"(a3), "r"(b0), "r"(b1));
}

// ---------------------------------------------------------------------------
// Kernel: prep (fused) + VW = V@WV + bV via tensor cores
// bf16 split: hi*hi + hi*lo + lo*hi.  Persistent 148 blocks x 256 threads.
// Shared layout (uint4 elements, row stride RS=52):
//   sB[n][ks*4+tg]  = {Whi(kb), Whi(kb+4), Wlo(kb), Wlo(kb+4)}, kb=ks*8+tg
//   sA[row][ks*4+tg] same for V rows (double-buffered).
// ---------------------------------------------------------------------------
__global__ void __launch_bounds__(256, 1)
vproj_kernel(const float* __restrict__ V, const float* __restrict__ WV,
             const float* __restrict__ bV,
             const float* __restrict__ R, const float* __restrict__ WR,
             const float* __restrict__ bR,
             const float* __restrict__ P, const float* __restrict__ WP,
             const float* __restrict__ bP) {
    extern __shared__ uint4 smem4[];
    uint4* sB = smem4;                    // 128*52 = 6656 uint4
    uint4* sA = smem4 + H * RS;           // 2 bufs * 32*52
    unsigned* sBu = (unsigned*)sB;
    unsigned* sAu = (unsigned*)sA;

    __shared__ float sR[8 * DR];          // prep staging (also holds P: 384 <= 1024)

    int tid = threadIdx.x;
    int w = tid >> 5, lane = tid & 31;
    int g = lane >> 2, tg = lane & 3;
    int rg = (w & 1) * 16;
    int nb = (w >> 1) * 32;
    int blk = blockIdx.x;

    // ---------------- fused prep: XR (blocks 0..124), pp (block 125) --------
    if (blk < 125) {
        int h = tid & 127;
        if (tid < 128) {
            #pragma unroll
            for (int k = 0; k < 8; k++) sR[k * DR + h] = R[(size_t)(8 * blk + k) * DR + h];
        }
        __syncthreads();
        if (tid < 128) {
            float acc[8];
            float bias = bR[h];
            #pragma unroll
            for (int k = 0; k < 8; k++) acc[k] = bias;
            #pragma unroll 4
            for (int d = 0; d < DR; d++) {
                float wv = WR[d * H + h];
                #pragma unroll
                for (int k = 0; k < 8; k++) acc[k] = fmaf(sR[k * DR + d], wv, acc[k]);
            }
            #pragma unroll
            for (int k = 0; k < 8; k++) g_XR[(size_t)(8 * blk + k) * H + h] = acc[k];
        }
        __syncthreads();
    } else if (blk == 125) {
        int h = tid & 127;
        if (tid < 128) {
            for (int i = h; i < ARITY * DR; i += 128) sR[i] = P[i];
        }
        __syncthreads();
        if (tid < 128) {
            float prod = 1.0f;
            for (int a = 0; a < ARITY; a++) {
                float acc = bP[h];
                #pragma unroll 4
                for (int d = 0; d < DR; d++) acc = fmaf(sR[a * DR + d], WP[d * H + h], acc);
                prod *= acc;
            }
            g_pp[h] = prod;
        }
        __syncthreads();
    }

    // ---------------- one-time: split W into shared -------------------------
    for (int idx = tid; idx < KK * H; idx += 256) {
        int kk = idx >> 7, n = idx & 127;
        unsigned hi, lo;
        split_pair(WV[(2 * kk) * H + n], WV[(2 * kk + 1) * H + n], hi, lo);
        int wd = (n * RS + (kk >> 3) * 4 + (kk & 3)) * 4 + ((kk >> 2) & 1);
        sBu[wd] = hi;
        sBu[wd + 2] = lo;
    }

    // bias registers (per-warp columns)
    float bvx[4], bvy[4];
    #pragma unroll
    for (int nt = 0; nt < 4; nt++) {
        int col = nb + nt * 8 + 2 * tg;
        bvx[nt] = bV[col];
        bvy[nt] = bV[col + 1];
    }

    // ---------------- prologue: convert first tile into buf 0 ---------------
    int t = blk;
    if (t < NTILES) {
        unsigned* dst = sAu;
        for (int j = 0; j < 12; j++) {
            int idx = tid + j * 256;           // 3072 = 12*256 exact
            int row = idx / KK, kk = idx - row * KK;
            float2 v = *(const float2*)(V + (size_t)(t * VT_ROWS + row) * DV + 2 * kk);
            unsigned hi, lo;
            split_pair(v.x, v.y, hi, lo);
            int wd = (row * RS + (kk >> 3) * 4 + (kk & 3)) * 4 + ((kk >> 2) & 1);
            dst[wd] = hi;
            dst[wd + 2] = lo;
        }
    }
    __syncthreads();

    int buf = 0;
    for (; t < NTILES; t += gridDim.x) {
        int tn = t + gridDim.x;
        // prefetch next tile into registers (LDGs overlap with MMA below)
        float2 pv[12];
        if (tn < NTILES) {
            #pragma unroll
            for (int j = 0; j < 12; j++) {
                int idx = tid + j * 256;
                int row = idx / KK, kk = idx - row * KK;
                pv[j] = *(const float2*)(V + (size_t)(tn * VT_ROWS + row) * DV + 2 * kk);
            }
        }

        // --- compute on current buffer ---
        const uint4* A = sA + buf * (VT_ROWS * RS);
        float c[4][4];
        #pragma unroll
        for (int nt = 0; nt < 4; nt++)
            #pragma unroll
            for (int i = 0; i < 4; i++) c[nt][i] = 0.f;

        int rowA = rg + g;
        #pragma unroll
        for (int ks = 0; ks < KSTEPS; ks++) {
            uint4 A0 = A[rowA * RS + ks * 4 + tg];         // {ah0, ah2, al0, al2}
            uint4 A1 = A[(rowA + 8) * RS + ks * 4 + tg];   // {ah1, ah3, al1, al3}
            #pragma unroll
            for (int nt = 0; nt < 4; nt++) {
                int nc = nb + nt * 8 + g;
                uint4 Bv = sB[nc * RS + ks * 4 + tg];      // {bh0, bh1, bl0, bl1}
                mma16816bf(c[nt], A0.x, A1.x, A0.y, A1.y, Bv.x, Bv.y);  // hi*hi
                mma16816bf(c[nt], A0.x, A1.x, A0.y, A1.y, Bv.z, Bv.w);  // hi*lo
                mma16816bf(c[nt], A0.z, A1.z, A0.w, A1.w, Bv.x, Bv.y);  // lo*hi
            }
        }

        // --- epilogue: store tile results (+bias) ---
        {
            int grow = t * VT_ROWS + rg + g;
            #pragma unroll
            for (int nt = 0; nt < 4; nt++) {
                int col = nb + nt * 8 + 2 * tg;
                float2 r0 = make_float2(c[nt][0] + bvx[nt], c[nt][1] + bvy[nt]);
                float2 r1 = make_float2(c[nt][2] + bvx[nt], c[nt][3] + bvy[nt]);
                *(float2*)(g_VW + (size_t)grow * H + col) = r0;
                *(float2*)(g_VW + (size_t)(grow + 8) * H + col) = r1;
            }
        }

        // --- convert prefetched tile into other buffer ---
        if (tn < NTILES) {
            unsigned* dst = sAu + (buf ^ 1) * (VT_ROWS * RS * 4);
            #pragma unroll
            for (int j = 0; j < 12; j++) {
                int idx = tid + j * 256;
                int row = idx / KK, kk = idx - row * KK;
                unsigned hi, lo;
                split_pair(pv[j].x, pv[j].y, hi, lo);
                int wd = (row * RS + (kk >> 3) * 4 + (kk & 3)) * 4 + ((kk >> 2) & 1);
                dst[wd] = hi;
                dst[wd + 2] = lo;
            }
        }
        __syncthreads();
        buf ^= 1;
    }
}

// ---------------------------------------------------------------------------
// Kernel: out[b,h] = pp[h] * sum_n XR[r[b,n],h] * VW[e0]*VW[e1]*VW[e2]
// float4 lanes: warp covers full 128-col row per LDG.128; 4 warps split n.
// ---------------------------------------------------------------------------
__global__ void __launch_bounds__(128)
gather_kernel(const int* __restrict__ r, const int* __restrict__ e,
              float* __restrict__ out) {
    __shared__ int sidx[4 * N];
    __shared__ float4 sacc[128];
    int tid = threadIdx.x;
    int w = tid >> 5, l = tid & 31;
    int b = blockIdx.x;
    for (int i = tid; i < 4 * N; i += 128) {
        int k = i >> 6, n = i & 63;
        sidx[i] = (k == 0) ? r[b * N + n] : e[(k - 1) * (B * N) + b * N + n];
    }
    __syncthreads();

    const float4* XR4 = (const float4*)g_XR;
    const float4* VW4 = (const float4*)g_VW;
    float4 acc = make_float4(0.f, 0.f, 0.f, 0.f);
    #pragma unroll 4
    for (int i = 0; i < 16; i++) {
        int n = w + i * 4;
        int ir = sidx[n];
        int i0 = sidx[64 + n];
        int i1 = sidx[128 + n];
        int i2 = sidx[192 + n];
        float4 xr = XR4[ir * 32 + l];
        float4 v0 = VW4[i0 * 32 + l];
        float4 v1 = VW4[i1 * 32 + l];
        float4 v2 = VW4[i2 * 32 + l];
        acc.x += xr.x * (v0.x * (v1.x * v2.x));
        acc.y += xr.y * (v0.y * (v1.y * v2.y));
        acc.z += xr.z * (v0.z * (v1.z * v2.z));
        acc.w += xr.w * (v0.w * (v1.w * v2.w));
    }
    sacc[tid] = acc;
    __syncthreads();
    if (w == 0) {
        float4 a0 = sacc[l], a1 = sacc[32 + l], a2 = sacc[64 + l], a3 = sacc[96 + l];
        float4 pp = ((const float4*)g_pp)[l];
        float4 o;
        o.x = (a0.x + a1.x + a2.x + a3.x) * pp.x;
        o.y = (a0.y + a1.y + a2.y + a3.y) * pp.y;
        o.z = (a0.z + a1.z + a2.z + a3.z) * pp.z;
        o.w = (a0.w + a1.w + a2.w + a3.w) * pp.w;
        ((float4*)out)[b * 32 + l] = o;
    }
}

// ---------------------------------------------------------------------------
extern "C" void kernel_launch(void* const* d_in, const int* in_sizes, int n_in,
                              void* d_out, int out_size) {
    const int*   r  = (const int*)d_in[0];
    const int*   e  = (const int*)d_in[1];
    const float* V  = (const float*)d_in[2];
    const float* R  = (const float*)d_in[3];
    const float* P  = (const float*)d_in[4];
    const float* WV = (const float*)d_in[5];
    const float* bV = (const float*)d_in[6];
    const float* WR = (const float*)d_in[7];
    const float* bR = (const float*)d_in[8];
    const float* WP = (const float*)d_in[9];
    const float* bP = (const float*)d_in[10];
    float* out = (float*)d_out;

    int smem = (H * RS + 2 * VT_ROWS * RS) * (int)sizeof(uint4);  // 159744 B
    cudaFuncSetAttribute(vproj_kernel, cudaFuncAttributeMaxDynamicSharedMemorySize, smem);

    vproj_kernel<<<148, 256, smem>>>(V, WV, bV, R, WR, bR, P, WP, bP);
    gather_kernel<<<B, 128>>>(r, e, out);
}

// round 7
// speedup vs baseline: 2.6297x; 1.0345x over previous
#include <cuda_runtime.h>
#include <cuda_fp16.h>

#define NUM_V 100000
#define NUM_R 1000
#define DV 192   // D+I (K dim of V projection)
#define DR 128
#define H 128
#define B 4096
#define N 64
#define ARITY 3

#define VT_ROWS 32                 // V rows per tile
#define NTILES  (NUM_V / VT_ROWS)  // 3125 (exact)
#define KSTEPS  (DV / 16)          // 12
#define KK      (DV / 2)           // 96 bf16x2 per row
#define RS      52                 // row stride in uint4 (52%8==4 -> conflict-free LDS.128)

__device__ __align__(16) float g_VW[NUM_V * H];   // 51.2 MB (L2-resident for gather)
__device__ __align__(16) float g_XR[NUM_R * H];
__device__ __align__(16) float g_pp[H];

// ---------------------------------------------------------------------------
// helpers
// ---------------------------------------------------------------------------
// Truncated-bf16 2-term split: hi = top 16 bits (exact), lo = rn-bf16(x - hi).
__device__ __forceinline__ void split_pair(float x, float y, unsigned& hi, unsigned& lo) {
    unsigned xb = __float_as_uint(x), yb = __float_as_uint(y);
    hi = __byte_perm(xb, yb, 0x7632);
    float lx = x - __uint_as_float(xb & 0xFFFF0000u);
    float ly = y - __uint_as_float(yb & 0xFFFF0000u);
    asm("cvt.rn.bf16x2.f32 %0, %1, %2;" : "=r"(lo) : "f"(ly), "f"(lx));
}

__device__ __forceinline__ void mma16816bf(float c[4],
                                           unsigned a0, unsigned a1, unsigned a2, unsigned a3,
                                           unsigned b0, unsigned b1) {
    asm volatile(
        "mma.sync.aligned.m16n8k16.row.col.f32.bf16.bf16.f32 "
        "{%0,%1,%2,%3},{%4,%5,%6,%7},{%8,%9},{%0,%1,%2,%3};\n"
        : "+f"(c[0]), "+f"(c[1]), "+f"(c[2]), "+f"(c[3])
        : "r"(a0), "r"(a1), "r"(a2), "r"(a3), "r"(b0), "r"(b1));
}

// ---------------------------------------------------------------------------
// Kernel: prep (fused) + VW = V@WV + bV via mma.sync bf16 split
// (hi*hi + hi*lo + lo*hi).  Persistent 148 blocks x 256 threads.
// W fragments are loop-invariant -> cached in registers (96 regs/thread);
// inner loop issues ONLY A-loads: 4 LDS.128 per ks, 12 MMA per ks.
// Each warp: all 32 tile rows x 16 output cols (nb = w*16).
// Shared: W staged once (128*RS uint4 = 104 KB), then reused as A double buffer
// (2 * 32*RS uint4 = 52 KB).
// ---------------------------------------------------------------------------
__global__ void __launch_bounds__(256, 1)
vproj_kernel(const float* __restrict__ V, const float* __restrict__ WV,
             const float* __restrict__ bV,
             const float* __restrict__ R, const float* __restrict__ WR,
             const float* __restrict__ bR,
             const float* __restrict__ P, const float* __restrict__ WP,
             const float* __restrict__ bP) {
    extern __shared__ uint4 smem4[];
    unsigned* smu = (unsigned*)smem4;
    __shared__ float sR[8 * DR];

    int tid = threadIdx.x;
    int w = tid >> 5, lane = tid & 31;
    int g = lane >> 2, tg = lane & 3;
    int nb = w * 16;
    int blk = blockIdx.x;

    // ---------------- fused prep: XR (blocks 0..124), pp (block 125) --------
    if (blk < 125) {
        int h = tid & 127;
        if (tid < 128) {
            #pragma unroll
            for (int k = 0; k < 8; k++) sR[k * DR + h] = R[(size_t)(8 * blk + k) * DR + h];
        }
        __syncthreads();
        if (tid < 128) {
            float acc[8];
            float bias = bR[h];
            #pragma unroll
            for (int k = 0; k < 8; k++) acc[k] = bias;
            #pragma unroll 4
            for (int d = 0; d < DR; d++) {
                float wv = WR[d * H + h];
                #pragma unroll
                for (int k = 0; k < 8; k++) acc[k] = fmaf(sR[k * DR + d], wv, acc[k]);
            }
            #pragma unroll
            for (int k = 0; k < 8; k++) g_XR[(size_t)(8 * blk + k) * H + h] = acc[k];
        }
        __syncthreads();
    } else if (blk == 125) {
        int h = tid & 127;
        if (tid < 128) {
            for (int i = h; i < ARITY * DR; i += 128) sR[i] = P[i];
        }
        __syncthreads();
        if (tid < 128) {
            float prod = 1.0f;
            for (int a = 0; a < ARITY; a++) {
                float acc = bP[h];
                #pragma unroll 4
                for (int d = 0; d < DR; d++) acc = fmaf(sR[a * DR + d], WP[d * H + h], acc);
                prod *= acc;
            }
            g_pp[h] = prod;
        }
        __syncthreads();
    }

    // ---------------- stage W split into shared (one-time) ------------------
    for (int idx = tid; idx < KK * H; idx += 256) {
        int kk = idx >> 7, n = idx & 127;
        unsigned hi, lo;
        split_pair(WV[(2 * kk) * H + n], WV[(2 * kk + 1) * H + n], hi, lo);
        int wd = (n * RS + (kk >> 3) * 4 + (kk & 3)) * 4 + ((kk >> 2) & 1);
        smu[wd] = hi;
        smu[wd + 2] = lo;
    }
    __syncthreads();

    // ---------------- load W fragments into registers -----------------------
    // Bf[ks][nt] = {bh0, bh1, bl0, bl1} for col group nc = nb + nt*8 + g
    uint4 Bf[KSTEPS][2];
    #pragma unroll
    for (int ks = 0; ks < KSTEPS; ks++) {
        #pragma unroll
        for (int nt = 0; nt < 2; nt++) {
            int nc = nb + nt * 8 + g;
            Bf[ks][nt] = smem4[nc * RS + ks * 4 + tg];
        }
    }
    // bias registers
    float bvx[2], bvy[2];
    #pragma unroll
    for (int nt = 0; nt < 2; nt++) {
        int col = nb + nt * 8 + 2 * tg;
        bvx[nt] = bV[col];
        bvy[nt] = bV[col + 1];
    }
    __syncthreads();   // all warps done reading W; smem becomes A double buffer

    // ---------------- prologue: convert first tile into buf 0 ---------------
    int t = blk;
    if (t < NTILES) {
        for (int j = 0; j < 12; j++) {
            int idx = tid + j * 256;           // 3072 = 12*256 exact
            int row = idx / KK, kk = idx - row * KK;
            float2 v = *(const float2*)(V + (size_t)(t * VT_ROWS + row) * DV + 2 * kk);
            unsigned hi, lo;
            split_pair(v.x, v.y, hi, lo);
            int wd = (row * RS + (kk >> 3) * 4 + (kk & 3)) * 4 + ((kk >> 2) & 1);
            smu[wd] = hi;
            smu[wd + 2] = lo;
        }
    }
    __syncthreads();

    int buf = 0;
    for (; t < NTILES; t += gridDim.x) {
        int tn = t + gridDim.x;
        // prefetch next tile into registers (LDGs overlap with MMA below)
        float2 pv[12];
        if (tn < NTILES) {
            #pragma unroll
            for (int j = 0; j < 12; j++) {
                int idx = tid + j * 256;
                int row = idx / KK, kk = idx - row * KK;
                pv[j] = *(const float2*)(V + (size_t)(tn * VT_ROWS + row) * DV + 2 * kk);
            }
        }

        // --- compute on current buffer: A loads only, B from registers ---
        const uint4* A = smem4 + buf * (VT_ROWS * RS);
        float c[2][2][4];
        #pragma unroll
        for (int rg = 0; rg < 2; rg++)
            #pragma unroll
            for (int nt = 0; nt < 2; nt++)
                #pragma unroll
                for (int i = 0; i < 4; i++) c[rg][nt][i] = 0.f;

        #pragma unroll
        for (int ks = 0; ks < KSTEPS; ks++) {
            uint4 A0a = A[(g)      * RS + ks * 4 + tg];   // rows g,    {ah0,ah2,al0,al2}
            uint4 A1a = A[(g + 8)  * RS + ks * 4 + tg];   // rows g+8,  {ah1,ah3,al1,al3}
            uint4 A0b = A[(g + 16) * RS + ks * 4 + tg];
            uint4 A1b = A[(g + 24) * RS + ks * 4 + tg];
            #pragma unroll
            for (int nt = 0; nt < 2; nt++) {
                uint4 Bv = Bf[ks][nt];
                mma16816bf(c[0][nt], A0a.x, A1a.x, A0a.y, A1a.y, Bv.x, Bv.y);  // hi*hi
                mma16816bf(c[0][nt], A0a.x, A1a.x, A0a.y, A1a.y, Bv.z, Bv.w);  // hi*lo
                mma16816bf(c[0][nt], A0a.z, A1a.z, A0a.w, A1a.w, Bv.x, Bv.y);  // lo*hi
                mma16816bf(c[1][nt], A0b.x, A1b.x, A0b.y, A1b.y, Bv.x, Bv.y);
                mma16816bf(c[1][nt], A0b.x, A1b.x, A0b.y, A1b.y, Bv.z, Bv.w);
                mma16816bf(c[1][nt], A0b.z, A1b.z, A0b.w, A1b.w, Bv.x, Bv.y);
            }
        }

        // --- epilogue: store tile results (+bias) ---
        #pragma unroll
        for (int rg = 0; rg < 2; rg++) {
            int grow = t * VT_ROWS + rg * 16 + g;
            #pragma unroll
            for (int nt = 0; nt < 2; nt++) {
                int col = nb + nt * 8 + 2 * tg;
                float2 r0 = make_float2(c[rg][nt][0] + bvx[nt], c[rg][nt][1] + bvy[nt]);
                float2 r1 = make_float2(c[rg][nt][2] + bvx[nt], c[rg][nt][3] + bvy[nt]);
                *(float2*)(g_VW + (size_t)grow * H + col) = r0;
                *(float2*)(g_VW + (size_t)(grow + 8) * H + col) = r1;
            }
        }

        // --- convert prefetched tile into other buffer ---
        if (tn < NTILES) {
            unsigned* dst = smu + (buf ^ 1) * (VT_ROWS * RS * 4);
            #pragma unroll
            for (int j = 0; j < 12; j++) {
                int idx = tid + j * 256;
                int row = idx / KK, kk = idx - row * KK;
                unsigned hi, lo;
                split_pair(pv[j].x, pv[j].y, hi, lo);
                int wd = (row * RS + (kk >> 3) * 4 + (kk & 3)) * 4 + ((kk >> 2) & 1);
                dst[wd] = hi;
                dst[wd + 2] = lo;
            }
        }
        __syncthreads();
        buf ^= 1;
    }
}

// ---------------------------------------------------------------------------
// Kernel: out[b,h] = pp[h] * sum_n XR[r[b,n],h] * VW[e0]*VW[e1]*VW[e2]
// float4 lanes: warp covers full 128-col row per LDG.128; 4 warps split n.
// ---------------------------------------------------------------------------
__global__ void __launch_bounds__(128)
gather_kernel(const int* __restrict__ r, const int* __restrict__ e,
              float* __restrict__ out) {
    __shared__ int sidx[4 * N];
    __shared__ float4 sacc[128];
    int tid = threadIdx.x;
    int w = tid >> 5, l = tid & 31;
    int b = blockIdx.x;
    for (int i = tid; i < 4 * N; i += 128) {
        int k = i >> 6, n = i & 63;
        sidx[i] = (k == 0) ? r[b * N + n] : e[(k - 1) * (B * N) + b * N + n];
    }
    __syncthreads();

    const float4* XR4 = (const float4*)g_XR;
    const float4* VW4 = (const float4*)g_VW;
    float4 acc = make_float4(0.f, 0.f, 0.f, 0.f);
    #pragma unroll 4
    for (int i = 0; i < 16; i++) {
        int n = w + i * 4;
        int ir = sidx[n];
        int i0 = sidx[64 + n];
        int i1 = sidx[128 + n];
        int i2 = sidx[192 + n];
        float4 xr = XR4[ir * 32 + l];
        float4 v0 = VW4[i0 * 32 + l];
        float4 v1 = VW4[i1 * 32 + l];
        float4 v2 = VW4[i2 * 32 + l];
        acc.x += xr.x * (v0.x * (v1.x * v2.x));
        acc.y += xr.y * (v0.y * (v1.y * v2.y));
        acc.z += xr.z * (v0.z * (v1.z * v2.z));
        acc.w += xr.w * (v0.w * (v1.w * v2.w));
    }
    sacc[tid] = acc;
    __syncthreads();
    if (w == 0) {
        float4 a0 = sacc[l], a1 = sacc[32 + l], a2 = sacc[64 + l], a3 = sacc[96 + l];
        float4 pp = ((const float4*)g_pp)[l];
        float4 o;
        o.x = (a0.x + a1.x + a2.x + a3.x) * pp.x;
        o.y = (a0.y + a1.y + a2.y + a3.y) * pp.y;
        o.z = (a0.z + a1.z + a2.z + a3.z) * pp.z;
        o.w = (a0.w + a1.w + a2.w + a3.w) * pp.w;
        ((float4*)out)[b * 32 + l] = o;
    }
}

// ---------------------------------------------------------------------------
extern "C" void kernel_launch(void* const* d_in, const int* in_sizes, int n_in,
                              void* d_out, int out_size) {
    const int*   r  = (const int*)d_in[0];
    const int*   e  = (const int*)d_in[1];
    const float* V  = (const float*)d_in[2];
    const float* R  = (const float*)d_in[3];
    const float* P  = (const float*)d_in[4];
    const float* WV = (const float*)d_in[5];
    const float* bV = (const float*)d_in[6];
    const float* WR = (const float*)d_in[7];
    const float* bR = (const float*)d_in[8];
    const float* WP = (const float*)d_in[9];
    const float* bP = (const float*)d_in[10];
    float* out = (float*)d_out;

    int smem = (H * RS) * (int)sizeof(uint4);   // 106496 B (W staging; >= 2 A buffers)
    cudaFuncSetAttribute(vproj_kernel, cudaFuncAttributeMaxDynamicSharedMemorySize, smem);

    vproj_kernel<<<148, 256, smem>>>(V, WV, bV, R, WR, bR, P, WP, bP);
    gather_kernel<<<B, 128>>>(r, e, out);
}

// round 8
// speedup vs baseline: 2.9190x; 1.1100x over previous
#include <cuda_runtime.h>
#include <cuda_fp16.h>

#define NUM_V 100000
#define NUM_R 1000
#define DV 192   // D+I (K dim of V projection)
#define DR 128
#define H 128
#define B 4096
#define N 64
#define ARITY 3

#define VT_ROWS 32                 // V rows per tile
#define NTILES  (NUM_V / VT_ROWS)  // 3125 (exact)
#define KSTEPS  (DV / 16)          // 12
#define KK      (DV / 2)           // 96 bf16x2 per row
#define RS      52                 // row stride in uint4 (52%8==4 -> conflict-free LDS.128)

__device__ __align__(16) __half g_VW[NUM_V * H];  // 25.6 MB fp16 (L2-resident for gather)
__device__ __align__(16) float  g_XR[NUM_R * H];
__device__ __align__(16) float  g_pp[H];

// ---------------------------------------------------------------------------
// helpers
// ---------------------------------------------------------------------------
// Truncated-bf16 2-term split: hi = top 16 bits (exact), lo = rn-bf16(x - hi).
__device__ __forceinline__ void split_pair(float x, float y, unsigned& hi, unsigned& lo) {
    unsigned xb = __float_as_uint(x), yb = __float_as_uint(y);
    hi = __byte_perm(xb, yb, 0x7632);
    float lx = x - __uint_as_float(xb & 0xFFFF0000u);
    float ly = y - __uint_as_float(yb & 0xFFFF0000u);
    asm("cvt.rn.bf16x2.f32 %0, %1, %2;" : "=r"(lo) : "f"(ly), "f"(lx));
}

__device__ __forceinline__ unsigned pack_h2(float lo, float hi) {
    unsigned r;
    asm("cvt.rn.f16x2.f32 %0, %1, %2;" : "=r"(r) : "f"(hi), "f"(lo));
    return r;
}

__device__ __forceinline__ void mma16816bf(float c[4],
                                           unsigned a0, unsigned a1, unsigned a2, unsigned a3,
                                           unsigned b0, unsigned b1) {
    asm volatile(
        "mma.sync.aligned.m16n8k16.row.col.f32.bf16.bf16.f32 "
        "{%0,%1,%2,%3},{%4,%5,%6,%7},{%8,%9},{%0,%1,%2,%3};\n"
        : "+f"(c[0]), "+f"(c[1]), "+f"(c[2]), "+f"(c[3])
        : "r"(a0), "r"(a1), "r"(a2), "r"(a3), "r"(b0), "r"(b1));
}

// ---------------------------------------------------------------------------
// Kernel: prep (fused) + VW = V@WV + bV via mma.sync bf16 split
// (hi*hi + hi*lo + lo*hi).  Persistent 148 blocks x 256 threads.
// W fragments cached in registers; inner loop: 4 LDS.128 + 12 MMA per ks.
// Output stored as fp16 (half2 pairs).
// ---------------------------------------------------------------------------
__global__ void __launch_bounds__(256, 1)
vproj_kernel(const float* __restrict__ V, const float* __restrict__ WV,
             const float* __restrict__ bV,
             const float* __restrict__ R, const float* __restrict__ WR,
             const float* __restrict__ bR,
             const float* __restrict__ P, const float* __restrict__ WP,
             const float* __restrict__ bP) {
    extern __shared__ uint4 smem4[];
    unsigned* smu = (unsigned*)smem4;
    __shared__ float sR[8 * DR];

    int tid = threadIdx.x;
    int w = tid >> 5, lane = tid & 31;
    int g = lane >> 2, tg = lane & 3;
    int nb = w * 16;
    int blk = blockIdx.x;

    // ---------------- fused prep: XR (blocks 0..124), pp (block 125) --------
    if (blk < 125) {
        int h = tid & 127;
        if (tid < 128) {
            #pragma unroll
            for (int k = 0; k < 8; k++) sR[k * DR + h] = R[(size_t)(8 * blk + k) * DR + h];
        }
        __syncthreads();
        if (tid < 128) {
            float acc[8];
            float bias = bR[h];
            #pragma unroll
            for (int k = 0; k < 8; k++) acc[k] = bias;
            #pragma unroll 4
            for (int d = 0; d < DR; d++) {
                float wv = WR[d * H + h];
                #pragma unroll
                for (int k = 0; k < 8; k++) acc[k] = fmaf(sR[k * DR + d], wv, acc[k]);
            }
            #pragma unroll
            for (int k = 0; k < 8; k++) g_XR[(size_t)(8 * blk + k) * H + h] = acc[k];
        }
        __syncthreads();
    } else if (blk == 125) {
        int h = tid & 127;
        if (tid < 128) {
            for (int i = h; i < ARITY * DR; i += 128) sR[i] = P[i];
        }
        __syncthreads();
        if (tid < 128) {
            float prod = 1.0f;
            for (int a = 0; a < ARITY; a++) {
                float acc = bP[h];
                #pragma unroll 4
                for (int d = 0; d < DR; d++) acc = fmaf(sR[a * DR + d], WP[d * H + h], acc);
                prod *= acc;
            }
            g_pp[h] = prod;
        }
        __syncthreads();
    }

    // ---------------- stage W split into shared (one-time) ------------------
    for (int idx = tid; idx < KK * H; idx += 256) {
        int kk = idx >> 7, n = idx & 127;
        unsigned hi, lo;
        split_pair(WV[(2 * kk) * H + n], WV[(2 * kk + 1) * H + n], hi, lo);
        int wd = (n * RS + (kk >> 3) * 4 + (kk & 3)) * 4 + ((kk >> 2) & 1);
        smu[wd] = hi;
        smu[wd + 2] = lo;
    }
    __syncthreads();

    // ---------------- load W fragments into registers -----------------------
    uint4 Bf[KSTEPS][2];
    #pragma unroll
    for (int ks = 0; ks < KSTEPS; ks++) {
        #pragma unroll
        for (int nt = 0; nt < 2; nt++) {
            int nc = nb + nt * 8 + g;
            Bf[ks][nt] = smem4[nc * RS + ks * 4 + tg];
        }
    }
    float bvx[2], bvy[2];
    #pragma unroll
    for (int nt = 0; nt < 2; nt++) {
        int col = nb + nt * 8 + 2 * tg;
        bvx[nt] = bV[col];
        bvy[nt] = bV[col + 1];
    }
    __syncthreads();   // smem becomes A double buffer

    // ---------------- prologue: convert first tile into buf 0 ---------------
    int t = blk;
    if (t < NTILES) {
        for (int j = 0; j < 12; j++) {
            int idx = tid + j * 256;           // 3072 = 12*256 exact
            int row = idx / KK, kk = idx - row * KK;
            float2 v = *(const float2*)(V + (size_t)(t * VT_ROWS + row) * DV + 2 * kk);
            unsigned hi, lo;
            split_pair(v.x, v.y, hi, lo);
            int wd = (row * RS + (kk >> 3) * 4 + (kk & 3)) * 4 + ((kk >> 2) & 1);
            smu[wd] = hi;
            smu[wd + 2] = lo;
        }
    }
    __syncthreads();

    int buf = 0;
    for (; t < NTILES; t += gridDim.x) {
        int tn = t + gridDim.x;
        float2 pv[12];
        if (tn < NTILES) {
            #pragma unroll
            for (int j = 0; j < 12; j++) {
                int idx = tid + j * 256;
                int row = idx / KK, kk = idx - row * KK;
                pv[j] = *(const float2*)(V + (size_t)(tn * VT_ROWS + row) * DV + 2 * kk);
            }
        }

        // --- compute on current buffer: A loads only, B from registers ---
        const uint4* A = smem4 + buf * (VT_ROWS * RS);
        float c[2][2][4];
        #pragma unroll
        for (int rg = 0; rg < 2; rg++)
            #pragma unroll
            for (int nt = 0; nt < 2; nt++)
                #pragma unroll
                for (int i = 0; i < 4; i++) c[rg][nt][i] = 0.f;

        #pragma unroll
        for (int ks = 0; ks < KSTEPS; ks++) {
            uint4 A0a = A[(g)      * RS + ks * 4 + tg];
            uint4 A1a = A[(g + 8)  * RS + ks * 4 + tg];
            uint4 A0b = A[(g + 16) * RS + ks * 4 + tg];
            uint4 A1b = A[(g + 24) * RS + ks * 4 + tg];
            #pragma unroll
            for (int nt = 0; nt < 2; nt++) {
                uint4 Bv = Bf[ks][nt];
                mma16816bf(c[0][nt], A0a.x, A1a.x, A0a.y, A1a.y, Bv.x, Bv.y);  // hi*hi
                mma16816bf(c[0][nt], A0a.x, A1a.x, A0a.y, A1a.y, Bv.z, Bv.w);  // hi*lo
                mma16816bf(c[0][nt], A0a.z, A1a.z, A0a.w, A1a.w, Bv.x, Bv.y);  // lo*hi
                mma16816bf(c[1][nt], A0b.x, A1b.x, A0b.y, A1b.y, Bv.x, Bv.y);
                mma16816bf(c[1][nt], A0b.x, A1b.x, A0b.y, A1b.y, Bv.z, Bv.w);
                mma16816bf(c[1][nt], A0b.z, A1b.z, A0b.w, A1b.w, Bv.x, Bv.y);
            }
        }

        // --- epilogue: store fp16 tile results (+bias) ---
        #pragma unroll
        for (int rg = 0; rg < 2; rg++) {
            int grow = t * VT_ROWS + rg * 16 + g;
            #pragma unroll
            for (int nt = 0; nt < 2; nt++) {
                int col = nb + nt * 8 + 2 * tg;
                unsigned p0 = pack_h2(c[rg][nt][0] + bvx[nt], c[rg][nt][1] + bvy[nt]);
                unsigned p1 = pack_h2(c[rg][nt][2] + bvx[nt], c[rg][nt][3] + bvy[nt]);
                *(unsigned*)(g_VW + (size_t)grow * H + col) = p0;
                *(unsigned*)(g_VW + (size_t)(grow + 8) * H + col) = p1;
            }
        }

        // --- convert prefetched tile into other buffer ---
        if (tn < NTILES) {
            unsigned* dst = smu + (buf ^ 1) * (VT_ROWS * RS * 4);
            #pragma unroll
            for (int j = 0; j < 12; j++) {
                int idx = tid + j * 256;
                int row = idx / KK, kk = idx - row * KK;
                unsigned hi, lo;
                split_pair(pv[j].x, pv[j].y, hi, lo);
                int wd = (row * RS + (kk >> 3) * 4 + (kk & 3)) * 4 + ((kk >> 2) & 1);
                dst[wd] = hi;
                dst[wd + 2] = lo;
            }
        }
        __syncthreads();
        buf ^= 1;
    }
}

// ---------------------------------------------------------------------------
// Kernel: out[b,h] = pp[h] * sum_n XR[r[b,n],h] * VW[e0]*VW[e1]*VW[e2]
// VW rows are fp16 (256 B): lane l covers h-cols 4l..4l+3 (uint2 = 4 halves).
// XR stays f32 (float4 per lane). 4 warps split n; shared reduction.
// ---------------------------------------------------------------------------
__global__ void __launch_bounds__(128)
gather_kernel(const int* __restrict__ r, const int* __restrict__ e,
              float* __restrict__ out) {
    __shared__ int sidx[4 * N];
    __shared__ float4 sacc[128];
    int tid = threadIdx.x;
    int w = tid >> 5, l = tid & 31;
    int b = blockIdx.x;
    for (int i = tid; i < 4 * N; i += 128) {
        int k = i >> 6, n = i & 63;
        sidx[i] = (k == 0) ? r[b * N + n] : e[(k - 1) * (B * N) + b * N + n];
    }
    __syncthreads();

    const float4* XR4 = (const float4*)g_XR;
    const uint2*  VW2 = (const uint2*)g_VW;   // 32 uint2 per 128-half row
    float4 acc = make_float4(0.f, 0.f, 0.f, 0.f);
    #pragma unroll 4
    for (int i = 0; i < 16; i++) {
        int n = w + i * 4;
        int ir = sidx[n];
        int i0 = sidx[64 + n];
        int i1 = sidx[128 + n];
        int i2 = sidx[192 + n];
        float4 xr = XR4[ir * 32 + l];
        uint2 u0 = VW2[i0 * 32 + l];
        uint2 u1 = VW2[i1 * 32 + l];
        uint2 u2 = VW2[i2 * 32 + l];
        float2 a0 = __half22float2(*(const __half2*)&u0.x);
        float2 b0 = __half22float2(*(const __half2*)&u0.y);
        float2 a1 = __half22float2(*(const __half2*)&u1.x);
        float2 b1 = __half22float2(*(const __half2*)&u1.y);
        float2 a2 = __half22float2(*(const __half2*)&u2.x);
        float2 b2 = __half22float2(*(const __half2*)&u2.y);
        acc.x += xr.x * (a0.x * (a1.x * a2.x));
        acc.y += xr.y * (a0.y * (a1.y * a2.y));
        acc.z += xr.z * (b0.x * (b1.x * b2.x));
        acc.w += xr.w * (b0.y * (b1.y * b2.y));
    }
    sacc[tid] = acc;
    __syncthreads();
    if (w == 0) {
        float4 a0 = sacc[l], a1 = sacc[32 + l], a2 = sacc[64 + l], a3 = sacc[96 + l];
        float4 pp = ((const float4*)g_pp)[l];
        float4 o;
        o.x = (a0.x + a1.x + a2.x + a3.x) * pp.x;
        o.y = (a0.y + a1.y + a2.y + a3.y) * pp.y;
        o.z = (a0.z + a1.z + a2.z + a3.z) * pp.z;
        o.w = (a0.w + a1.w + a2.w + a3.w) * pp.w;
        ((float4*)out)[b * 32 + l] = o;
    }
}

// ---------------------------------------------------------------------------
extern "C" void kernel_launch(void* const* d_in, const int* in_sizes, int n_in,
                              void* d_out, int out_size) {
    const int*   r  = (const int*)d_in[0];
    const int*   e  = (const int*)d_in[1];
    const float* V  = (const float*)d_in[2];
    const float* R  = (const float*)d_in[3];
    const float* P  = (const float*)d_in[4];
    const float* WV = (const float*)d_in[5];
    const float* bV = (const float*)d_in[6];
    const float* WR = (const float*)d_in[7];
    const float* bR = (const float*)d_in[8];
    const float* WP = (const float*)d_in[9];
    const float* bP = (const float*)d_in[10];
    float* out = (float*)d_out;

    int smem = (H * RS) * (int)sizeof(uint4);   // 106496 B (W staging; >= 2 A buffers)
    cudaFuncSetAttribute(vproj_kernel, cudaFuncAttributeMaxDynamicSharedMemorySize, smem);

    vproj_kernel<<<148, 256, smem>>>(V, WV, bV, R, WR, bR, P, WP, bP);
    gather_kernel<<<B, 128>>>(r, e, out);
}

// round 9
// speedup vs baseline: 3.5730x; 1.2240x over previous
#include <cuda_runtime.h>
#include <cuda_fp16.h>

#define NUM_V 100000
#define NUM_R 1000
#define DV 192   // D+I (K dim of V projection)
#define DR 128
#define H 128
#define B 4096
#define N 64
#define ARITY 3

#define VT_ROWS 32                 // V rows per tile
#define NTILES  (NUM_V / VT_ROWS)  // 3125 (exact)
#define KSTEPS  (DV / 16)          // 12
#define NJ      (KSTEPS / 2)       // 6 (two K-steps packed per uint4)
#define KK      (DV / 2)           // 96 half2 per row
#define RS2     28                 // row stride in uint4 (28%8==4 -> conflict-free LDS.128)

__device__ __align__(16) __half g_VW[NUM_V * H];  // 25.6 MB fp16 (L2-resident for gather)
__device__ __align__(16) float  g_XR[NUM_R * H];
__device__ __align__(16) float  g_pp[H];

// ---------------------------------------------------------------------------
// helpers
// ---------------------------------------------------------------------------
__device__ __forceinline__ unsigned pack_h2(float lo, float hi) {
    unsigned r;
    asm("cvt.rn.f16x2.f32 %0, %1, %2;" : "=r"(r) : "f"(hi), "f"(lo));
    return r;
}

__device__ __forceinline__ void mma16816f16(float c[4],
                                            unsigned a0, unsigned a1, unsigned a2, unsigned a3,
                                            unsigned b0, unsigned b1) {
    asm volatile(
        "mma.sync.aligned.m16n8k16.row.col.f32.f16.f16.f32 "
        "{%0,%1,%2,%3},{%4,%5,%6,%7},{%8,%9},{%0,%1,%2,%3};\n"
        : "+f"(c[0]), "+f"(c[1]), "+f"(c[2]), "+f"(c[3])
        : "r"(a0), "r"(a1), "r"(a2), "r"(a3), "r"(b0), "r"(b1));
}

// word index (in unsigned units) for half2-col kk of a row, packed layout:
// uint4 entry (row, j=ks/2, tg) = {ks_even kb, ks_even kb+4, ks_odd kb, ks_odd kb+4}
__device__ __forceinline__ int wslot(int row, int kk) {
    return (row * RS2 + (kk >> 4) * 4 + (kk & 3)) * 4
         + (((kk >> 3) & 1) * 2 + ((kk >> 2) & 1));
}

// ---------------------------------------------------------------------------
// Kernel: prep (fused) + VW = V@WV + bV via single fp16 mma.sync.
// Persistent 148 blocks x 256 threads. W fragments cached in registers
// (48 regs); inner loop: 4 LDS.128 + 8 MMA per j (6 j's per tile).
// Output stored as fp16.
// ---------------------------------------------------------------------------
__global__ void __launch_bounds__(256, 1)
vproj_kernel(const float* __restrict__ V, const float* __restrict__ WV,
             const float* __restrict__ bV,
             const float* __restrict__ R, const float* __restrict__ WR,
             const float* __restrict__ bR,
             const float* __restrict__ P, const float* __restrict__ WP,
             const float* __restrict__ bP) {
    extern __shared__ uint4 smem4[];
    unsigned* smu = (unsigned*)smem4;
    __shared__ float sR[8 * DR];

    int tid = threadIdx.x;
    int w = tid >> 5, lane = tid & 31;
    int g = lane >> 2, tg = lane & 3;
    int nb = w * 16;
    int blk = blockIdx.x;

    // ---------------- fused prep: XR (blocks 0..124), pp (block 125) --------
    if (blk < 125) {
        int h = tid & 127;
        if (tid < 128) {
            #pragma unroll
            for (int k = 0; k < 8; k++) sR[k * DR + h] = R[(size_t)(8 * blk + k) * DR + h];
        }
        __syncthreads();
        if (tid < 128) {
            float acc[8];
            float bias = bR[h];
            #pragma unroll
            for (int k = 0; k < 8; k++) acc[k] = bias;
            #pragma unroll 4
            for (int d = 0; d < DR; d++) {
                float wv = WR[d * H + h];
                #pragma unroll
                for (int k = 0; k < 8; k++) acc[k] = fmaf(sR[k * DR + d], wv, acc[k]);
            }
            #pragma unroll
            for (int k = 0; k < 8; k++) g_XR[(size_t)(8 * blk + k) * H + h] = acc[k];
        }
        __syncthreads();
    } else if (blk == 125) {
        int h = tid & 127;
        if (tid < 128) {
            for (int i = h; i < ARITY * DR; i += 128) sR[i] = P[i];
        }
        __syncthreads();
        if (tid < 128) {
            float prod = 1.0f;
            for (int a = 0; a < ARITY; a++) {
                float acc = bP[h];
                #pragma unroll 4
                for (int d = 0; d < DR; d++) acc = fmaf(sR[a * DR + d], WP[d * H + h], acc);
                prod *= acc;
            }
            g_pp[h] = prod;
        }
        __syncthreads();
    }

    // ---------------- stage W (fp16) into shared (one-time) -----------------
    for (int idx = tid; idx < KK * H; idx += 256) {
        int kk = idx >> 7, n = idx & 127;
        smu[wslot(n, kk)] = pack_h2(WV[(2 * kk) * H + n], WV[(2 * kk + 1) * H + n]);
    }
    __syncthreads();

    // ---------------- load W fragments into registers -----------------------
    uint4 Bf[NJ][2];
    #pragma unroll
    for (int j = 0; j < NJ; j++) {
        #pragma unroll
        for (int nt = 0; nt < 2; nt++) {
            int nc = nb + nt * 8 + g;
            Bf[j][nt] = smem4[nc * RS2 + j * 4 + tg];
        }
    }
    float bvx[2], bvy[2];
    #pragma unroll
    for (int nt = 0; nt < 2; nt++) {
        int col = nb + nt * 8 + 2 * tg;
        bvx[nt] = bV[col];
        bvy[nt] = bV[col + 1];
    }
    __syncthreads();   // smem becomes A double buffer (2 * 32*RS2 uint4)

    // ---------------- prologue: convert first tile into buf 0 ---------------
    int t = blk;
    if (t < NTILES) {
        for (int j = 0; j < 12; j++) {
            int idx = tid + j * 256;           // 3072 = 12*256 exact
            int row = idx / KK, kk = idx - row * KK;
            float2 v = *(const float2*)(V + (size_t)(t * VT_ROWS + row) * DV + 2 * kk);
            smu[wslot(row, kk)] = pack_h2(v.x, v.y);
        }
    }
    __syncthreads();

    int buf = 0;
    for (; t < NTILES; t += gridDim.x) {
        int tn = t + gridDim.x;
        float2 pv[12];
        if (tn < NTILES) {
            #pragma unroll
            for (int j = 0; j < 12; j++) {
                int idx = tid + j * 256;
                int row = idx / KK, kk = idx - row * KK;
                pv[j] = *(const float2*)(V + (size_t)(tn * VT_ROWS + row) * DV + 2 * kk);
            }
        }

        // --- compute on current buffer: A loads only, B from registers ---
        const uint4* A = smem4 + buf * (VT_ROWS * RS2);
        float c[2][2][4];
        #pragma unroll
        for (int rg = 0; rg < 2; rg++)
            #pragma unroll
            for (int nt = 0; nt < 2; nt++)
                #pragma unroll
                for (int i = 0; i < 4; i++) c[rg][nt][i] = 0.f;

        #pragma unroll
        for (int j = 0; j < NJ; j++) {
            uint4 A0a = A[(g)      * RS2 + j * 4 + tg];
            uint4 A1a = A[(g + 8)  * RS2 + j * 4 + tg];
            uint4 A0b = A[(g + 16) * RS2 + j * 4 + tg];
            uint4 A1b = A[(g + 24) * RS2 + j * 4 + tg];
            #pragma unroll
            for (int nt = 0; nt < 2; nt++) {
                uint4 Bv = Bf[j][nt];
                // ks even (components x,y)
                mma16816f16(c[0][nt], A0a.x, A1a.x, A0a.y, A1a.y, Bv.x, Bv.y);
                mma16816f16(c[1][nt], A0b.x, A1b.x, A0b.y, A1b.y, Bv.x, Bv.y);
                // ks odd (components z,w)
                mma16816f16(c[0][nt], A0a.z, A1a.z, A0a.w, A1a.w, Bv.z, Bv.w);
                mma16816f16(c[1][nt], A0b.z, A1b.z, A0b.w, A1b.w, Bv.z, Bv.w);
            }
        }

        // --- epilogue: store fp16 tile results (+bias) ---
        #pragma unroll
        for (int rg = 0; rg < 2; rg++) {
            int grow = t * VT_ROWS + rg * 16 + g;
            #pragma unroll
            for (int nt = 0; nt < 2; nt++) {
                int col = nb + nt * 8 + 2 * tg;
                unsigned p0 = pack_h2(c[rg][nt][0] + bvx[nt], c[rg][nt][1] + bvy[nt]);
                unsigned p1 = pack_h2(c[rg][nt][2] + bvx[nt], c[rg][nt][3] + bvy[nt]);
                *(unsigned*)(g_VW + (size_t)grow * H + col) = p0;
                *(unsigned*)(g_VW + (size_t)(grow + 8) * H + col) = p1;
            }
        }

        // --- convert prefetched tile into other buffer ---
        if (tn < NTILES) {
            unsigned* dst = smu + (buf ^ 1) * (VT_ROWS * RS2 * 4);
            #pragma unroll
            for (int j = 0; j < 12; j++) {
                int idx = tid + j * 256;
                int row = idx / KK, kk = idx - row * KK;
                dst[wslot(row, kk)] = pack_h2(pv[j].x, pv[j].y);
            }
        }
        __syncthreads();
        buf ^= 1;
    }
}

// ---------------------------------------------------------------------------
// Kernel: out[b,h] = pp[h] * sum_n XR[r[b,n],h] * VW[e0]*VW[e1]*VW[e2]
// VW rows are fp16 (256 B): lane l covers h-cols 4l..4l+3 (uint2 = 4 halves).
// XR stays f32 (float4 per lane). 4 warps split n; shared reduction.
// ---------------------------------------------------------------------------
__global__ void __launch_bounds__(128)
gather_kernel(const int* __restrict__ r, const int* __restrict__ e,
              float* __restrict__ out) {
    __shared__ int sidx[4 * N];
    __shared__ float4 sacc[128];
    int tid = threadIdx.x;
    int w = tid >> 5, l = tid & 31;
    int b = blockIdx.x;
    for (int i = tid; i < 4 * N; i += 128) {
        int k = i >> 6, n = i & 63;
        sidx[i] = (k == 0) ? r[b * N + n] : e[(k - 1) * (B * N) + b * N + n];
    }
    __syncthreads();

    const float4* XR4 = (const float4*)g_XR;
    const uint2*  VW2 = (const uint2*)g_VW;   // 32 uint2 per 128-half row
    float4 acc = make_float4(0.f, 0.f, 0.f, 0.f);
    #pragma unroll 4
    for (int i = 0; i < 16; i++) {
        int n = w + i * 4;
        int ir = sidx[n];
        int i0 = sidx[64 + n];
        int i1 = sidx[128 + n];
        int i2 = sidx[192 + n];
        float4 xr = XR4[ir * 32 + l];
        uint2 u0 = VW2[i0 * 32 + l];
        uint2 u1 = VW2[i1 * 32 + l];
        uint2 u2 = VW2[i2 * 32 + l];
        float2 a0 = __half22float2(*(const __half2*)&u0.x);
        float2 b0 = __half22float2(*(const __half2*)&u0.y);
        float2 a1 = __half22float2(*(const __half2*)&u1.x);
        float2 b1 = __half22float2(*(const __half2*)&u1.y);
        float2 a2 = __half22float2(*(const __half2*)&u2.x);
        float2 b2 = __half22float2(*(const __half2*)&u2.y);
        acc.x += xr.x * (a0.x * (a1.x * a2.x));
        acc.y += xr.y * (a0.y * (a1.y * a2.y));
        acc.z += xr.z * (b0.x * (b1.x * b2.x));
        acc.w += xr.w * (b0.y * (b1.y * b2.y));
    }
    sacc[tid] = acc;
    __syncthreads();
    if (w == 0) {
        float4 a0 = sacc[l], a1 = sacc[32 + l], a2 = sacc[64 + l], a3 = sacc[96 + l];
        float4 pp = ((const float4*)g_pp)[l];
        float4 o;
        o.x = (a0.x + a1.x + a2.x + a3.x) * pp.x;
        o.y = (a0.y + a1.y + a2.y + a3.y) * pp.y;
        o.z = (a0.z + a1.z + a2.z + a3.z) * pp.z;
        o.w = (a0.w + a1.w + a2.w + a3.w) * pp.w;
        ((float4*)out)[b * 32 + l] = o;
    }
}

// ---------------------------------------------------------------------------
extern "C" void kernel_launch(void* const* d_in, const int* in_sizes, int n_in,
                              void* d_out, int out_size) {
    const int*   r  = (const int*)d_in[0];
    const int*   e  = (const int*)d_in[1];
    const float* V  = (const float*)d_in[2];
    const float* R  = (const float*)d_in[3];
    const float* P  = (const float*)d_in[4];
    const float* WV = (const float*)d_in[5];
    const float* bV = (const float*)d_in[6];
    const float* WR = (const float*)d_in[7];
    const float* bR = (const float*)d_in[8];
    const float* WP = (const float*)d_in[9];
    const float* bP = (const float*)d_in[10];
    float* out = (float*)d_out;

    int smem = (H * RS2) * (int)sizeof(uint4);   // 57344 B (W staging; >= 2 A buffers)
    cudaFuncSetAttribute(vproj_kernel, cudaFuncAttributeMaxDynamicSharedMemorySize, smem);

    vproj_kernel<<<148, 256, smem>>>(V, WV, bV, R, WR, bR, P, WP, bP);
    gather_kernel<<<B, 128>>>(r, e, out);
}

// round 10
// speedup vs baseline: 3.8110x; 1.0666x over previous
#include <cuda_runtime.h>
#include <cuda_fp16.h>

#define NUM_V 100000
#define NUM_R 1000
#define DV 192   // D+I (K dim of V projection)
#define DR 128
#define H 128
#define B 4096
#define N 64
#define ARITY 3

#define VT_ROWS 64                     // V rows per tile
#define NTILES  ((NUM_V + VT_ROWS - 1) / VT_ROWS)  // 1563 (last tile: 32 valid rows)
#define KSTEPS  12                     // 192 / 16
#define NJ      6                      // two K-steps packed per uint4
#define KK      96                     // half2 per row
#define RS2     28                     // row stride in uint4 (28%8==4 -> conflict-free LDS.128)

// smem map (uint4 units): A double buffer [0, 3584), stage [3584, 4672)
#define A_BUF_U4   (VT_ROWS * RS2)     // 1792
#define STAGE_U4   3584
#define STAGE_ROWW 68                  // stage row stride in 4B words (68%32==4)
#define SMEM_BYTES ((STAGE_U4 + VT_ROWS * 17) * 16)   // 74752

__device__ __align__(16) __half g_VW[NUM_V * H];  // 25.6 MB fp16
__device__ __align__(16) __half g_XR[NUM_R * H];  // fp16 (halves gather XR traffic)
__device__ __align__(16) float  g_pp[H];

// ---------------------------------------------------------------------------
// helpers
// ---------------------------------------------------------------------------
__device__ __forceinline__ unsigned pack_h2(float lo, float hi) {
    unsigned r;
    asm("cvt.rn.f16x2.f32 %0, %1, %2;" : "=r"(r) : "f"(hi), "f"(lo));
    return r;
}

__device__ __forceinline__ void mma16816f16(float c[4],
                                            unsigned a0, unsigned a1, unsigned a2, unsigned a3,
                                            unsigned b0, unsigned b1) {
    asm volatile(
        "mma.sync.aligned.m16n8k16.row.col.f32.f16.f16.f32 "
        "{%0,%1,%2,%3},{%4,%5,%6,%7},{%8,%9},{%0,%1,%2,%3};\n"
        : "+f"(c[0]), "+f"(c[1]), "+f"(c[2]), "+f"(c[3])
        : "r"(a0), "r"(a1), "r"(a2), "r"(a3), "r"(b0), "r"(b1));
}

// word index (unsigned units) for half2-col kk of a row; packed layout:
// uint4 (row, j=ks/2, tg) = {ks_even kb, ks_even kb+4, ks_odd kb, ks_odd kb+4}
__device__ __forceinline__ int wslot(int row, int kk) {
    return (row * RS2 + (kk >> 4) * 4 + (kk & 3)) * 4
         + (((kk >> 3) & 1) * 2 + ((kk >> 2) & 1));
}

// ---------------------------------------------------------------------------
// Kernel: prep (fused) + VW = V@WV + bV via fp16 mma.sync.
// Persistent 148 blocks x 256 threads, 64-row tiles, W fragments in registers,
// coalesced epilogue through padded smem staging. Output fp16.
// ---------------------------------------------------------------------------
__global__ void __launch_bounds__(256, 1)
vproj_kernel(const float* __restrict__ V, const float* __restrict__ WV,
             const float* __restrict__ bV,
             const float* __restrict__ R, const float* __restrict__ WR,
             const float* __restrict__ bR,
             const float* __restrict__ P, const float* __restrict__ WP,
             const float* __restrict__ bP) {
    extern __shared__ uint4 smem4[];
    unsigned* smu = (unsigned*)smem4;
    __shared__ float sR[8 * DR];

    int tid = threadIdx.x;
    int w = tid >> 5, lane = tid & 31;
    int g = lane >> 2, tg = lane & 3;
    int nb = w * 16;
    int blk = blockIdx.x;

    // ---------------- fused prep: XR (blocks 0..124), pp (block 125) --------
    if (blk < 125) {
        int h = tid & 127;
        if (tid < 128) {
            #pragma unroll
            for (int k = 0; k < 8; k++) sR[k * DR + h] = R[(size_t)(8 * blk + k) * DR + h];
        }
        __syncthreads();
        if (tid < 128) {
            float acc[8];
            float bias = bR[h];
            #pragma unroll
            for (int k = 0; k < 8; k++) acc[k] = bias;
            #pragma unroll 4
            for (int d = 0; d < DR; d++) {
                float wv = WR[d * H + h];
                #pragma unroll
                for (int k = 0; k < 8; k++) acc[k] = fmaf(sR[k * DR + d], wv, acc[k]);
            }
            #pragma unroll
            for (int k = 0; k < 8; k++)
                g_XR[(size_t)(8 * blk + k) * H + h] = __float2half_rn(acc[k]);
        }
        __syncthreads();
    } else if (blk == 125) {
        int h = tid & 127;
        if (tid < 128) {
            for (int i = h; i < ARITY * DR; i += 128) sR[i] = P[i];
        }
        __syncthreads();
        if (tid < 128) {
            float prod = 1.0f;
            for (int a = 0; a < ARITY; a++) {
                float acc = bP[h];
                #pragma unroll 4
                for (int d = 0; d < DR; d++) acc = fmaf(sR[a * DR + d], WP[d * H + h], acc);
                prod *= acc;
            }
            g_pp[h] = prod;
        }
        __syncthreads();
    }

    // ---------------- stage W (fp16) into shared (one-time) -----------------
    for (int idx = tid; idx < KK * H; idx += 256) {
        int kk = idx >> 7, n = idx & 127;
        smu[wslot(n, kk)] = pack_h2(WV[(2 * kk) * H + n], WV[(2 * kk + 1) * H + n]);
    }
    __syncthreads();

    // ---------------- load W fragments into registers -----------------------
    uint4 Bf[NJ][2];
    #pragma unroll
    for (int j = 0; j < NJ; j++) {
        #pragma unroll
        for (int nt = 0; nt < 2; nt++) {
            int nc = nb + nt * 8 + g;
            Bf[j][nt] = smem4[nc * RS2 + j * 4 + tg];
        }
    }
    float bvx[2], bvy[2];
    #pragma unroll
    for (int nt = 0; nt < 2; nt++) {
        int col = nb + nt * 8 + 2 * tg;
        bvx[nt] = bV[col];
        bvy[nt] = bV[col + 1];
    }
    __syncthreads();   // smem becomes A double buffer + stage

    // ---------------- prologue: convert first tile into buf 0 ---------------
    int t = blk;
    if (t < NTILES) {
        for (int j = 0; j < 24; j++) {
            int idx = tid + j * 256;           // 6144 = 24*256 exact
            int row = idx / KK, kk = idx - row * KK;
            int gr = t * VT_ROWS + row;
            if (gr >= NUM_V) gr = NUM_V - 1;
            float2 v = *(const float2*)(V + (size_t)gr * DV + 2 * kk);
            smu[wslot(row, kk)] = pack_h2(v.x, v.y);
        }
    }
    __syncthreads();

    int buf = 0;
    for (; t < NTILES; t += gridDim.x) {
        int tn = t + gridDim.x;
        float2 pv[24];
        if (tn < NTILES) {
            #pragma unroll
            for (int j = 0; j < 24; j++) {
                int idx = tid + j * 256;
                int row = idx / KK, kk = idx - row * KK;
                int gr = tn * VT_ROWS + row;
                if (gr >= NUM_V) gr = NUM_V - 1;
                pv[j] = *(const float2*)(V + (size_t)gr * DV + 2 * kk);
            }
        }

        // --- compute on current buffer: A loads only, B from registers ---
        const uint4* A = smem4 + buf * A_BUF_U4;
        float c[4][2][4];
        #pragma unroll
        for (int rg = 0; rg < 4; rg++)
            #pragma unroll
            for (int nt = 0; nt < 2; nt++)
                #pragma unroll
                for (int i = 0; i < 4; i++) c[rg][nt][i] = 0.f;

        #pragma unroll
        for (int j = 0; j < NJ; j++) {
            uint4 Af[8];
            #pragma unroll
            for (int r = 0; r < 8; r++)
                Af[r] = A[(g + 8 * r) * RS2 + j * 4 + tg];
            #pragma unroll
            for (int rg = 0; rg < 4; rg++) {
                uint4 A0 = Af[2 * rg], A1 = Af[2 * rg + 1];
                #pragma unroll
                for (int nt = 0; nt < 2; nt++) {
                    uint4 Bv = Bf[j][nt];
                    mma16816f16(c[rg][nt], A0.x, A1.x, A0.y, A1.y, Bv.x, Bv.y);  // ks even
                    mma16816f16(c[rg][nt], A0.z, A1.z, A0.w, A1.w, Bv.z, Bv.w);  // ks odd
                }
            }
        }

        // --- epilogue part 1: accumulators (+bias, fp16) -> padded stage ----
        {
            unsigned* stg = (unsigned*)(smem4 + STAGE_U4);
            #pragma unroll
            for (int rg = 0; rg < 4; rg++) {
                int r0 = rg * 16 + g;
                #pragma unroll
                for (int nt = 0; nt < 2; nt++) {
                    int cw = ((nb >> 1) + nt * 4 + tg);   // half2 column index
                    unsigned p0 = pack_h2(c[rg][nt][0] + bvx[nt], c[rg][nt][1] + bvy[nt]);
                    unsigned p1 = pack_h2(c[rg][nt][2] + bvx[nt], c[rg][nt][3] + bvy[nt]);
                    stg[r0 * STAGE_ROWW + cw] = p0;
                    stg[(r0 + 8) * STAGE_ROWW + cw] = p1;
                }
            }
        }

        // --- convert prefetched tile into other buffer ---
        if (tn < NTILES) {
            unsigned* dst = smu + (buf ^ 1) * (A_BUF_U4 * 4);
            #pragma unroll
            for (int j = 0; j < 24; j++) {
                int idx = tid + j * 256;
                int row = idx / KK, kk = idx - row * KK;
                dst[wslot(row, kk)] = pack_h2(pv[j].x, pv[j].y);
            }
        }
        __syncthreads();

        // --- epilogue part 2: coalesced copy-out (stage -> g_VW) ------------
        {
            const uint4* stg4 = smem4 + STAGE_U4;
            uint4* out4 = (uint4*)g_VW;
            #pragma unroll
            for (int k = 0; k < 4; k++) {
                int idx = tid + k * 256;        // 1024 = 64 rows * 16 uint4
                int row = idx >> 4, q = idx & 15;
                int grow = t * VT_ROWS + row;
                if (grow < NUM_V)
                    out4[(size_t)grow * 16 + q] = stg4[row * 17 + q];
            }
        }
        __syncthreads();
        buf ^= 1;
    }
}

// ---------------------------------------------------------------------------
// Kernel: out[b,h] = pp[h] * sum_n XR[r[b,n],h] * VW[e0]*VW[e1]*VW[e2]
// XR and VW rows fp16 (256 B): lane l covers h-cols 4l..4l+3 (uint2).
// 4 warps split n; shared reduction; pp f32.
// ---------------------------------------------------------------------------
__global__ void __launch_bounds__(128)
gather_kernel(const int* __restrict__ r, const int* __restrict__ e,
              float* __restrict__ out) {
    __shared__ int sidx[4 * N];
    __shared__ float4 sacc[128];
    int tid = threadIdx.x;
    int w = tid >> 5, l = tid & 31;
    int b = blockIdx.x;
    for (int i = tid; i < 4 * N; i += 128) {
        int k = i >> 6, n = i & 63;
        sidx[i] = (k == 0) ? r[b * N + n] : e[(k - 1) * (B * N) + b * N + n];
    }
    __syncthreads();

    const uint2* XR2 = (const uint2*)g_XR;
    const uint2* VW2 = (const uint2*)g_VW;
    float4 acc = make_float4(0.f, 0.f, 0.f, 0.f);
    #pragma unroll 4
    for (int i = 0; i < 16; i++) {
        int n = w + i * 4;
        int ir = sidx[n];
        int i0 = sidx[64 + n];
        int i1 = sidx[128 + n];
        int i2 = sidx[192 + n];
        uint2 ux = XR2[ir * 32 + l];
        uint2 u0 = VW2[i0 * 32 + l];
        uint2 u1 = VW2[i1 * 32 + l];
        uint2 u2 = VW2[i2 * 32 + l];
        float2 xa = __half22float2(*(const __half2*)&ux.x);
        float2 xb = __half22float2(*(const __half2*)&ux.y);
        float2 a0 = __half22float2(*(const __half2*)&u0.x);
        float2 b0 = __half22float2(*(const __half2*)&u0.y);
        float2 a1 = __half22float2(*(const __half2*)&u1.x);
        float2 b1 = __half22float2(*(const __half2*)&u1.y);
        float2 a2 = __half22float2(*(const __half2*)&u2.x);
        float2 b2 = __half22float2(*(const __half2*)&u2.y);
        acc.x += xa.x * (a0.x * (a1.x * a2.x));
        acc.y += xa.y * (a0.y * (a1.y * a2.y));
        acc.z += xb.x * (b0.x * (b1.x * b2.x));
        acc.w += xb.y * (b0.y * (b1.y * b2.y));
    }
    sacc[tid] = acc;
    __syncthreads();
    if (w == 0) {
        float4 a0 = sacc[l], a1 = sacc[32 + l], a2 = sacc[64 + l], a3 = sacc[96 + l];
        float4 pp = ((const float4*)g_pp)[l];
        float4 o;
        o.x = (a0.x + a1.x + a2.x + a3.x) * pp.x;
        o.y = (a0.y + a1.y + a2.y + a3.y) * pp.y;
        o.z = (a0.z + a1.z + a2.z + a3.z) * pp.z;
        o.w = (a0.w + a1.w + a2.w + a3.w) * pp.w;
        ((float4*)out)[b * 32 + l] = o;
    }
}

// ---------------------------------------------------------------------------
extern "C" void kernel_launch(void* const* d_in, const int* in_sizes, int n_in,
                              void* d_out, int out_size) {
    const int*   r  = (const int*)d_in[0];
    const int*   e  = (const int*)d_in[1];
    const float* V  = (const float*)d_in[2];
    const float* R  = (const float*)d_in[3];
    const float* P  = (const float*)d_in[4];
    const float* WV = (const float*)d_in[5];
    const float* bV = (const float*)d_in[6];
    const float* WR = (const float*)d_in[7];
    const float* bR = (const float*)d_in[8];
    const float* WP = (const float*)d_in[9];
    const float* bP = (const float*)d_in[10];
    float* out = (float*)d_out;

    cudaFuncSetAttribute(vproj_kernel, cudaFuncAttributeMaxDynamicSharedMemorySize, SMEM_BYTES);

    vproj_kernel<<<148, 256, SMEM_BYTES>>>(V, WV, bV, R, WR, bR, P, WP, bP);
    gather_kernel<<<B, 128>>>(r, e, out);
}

// round 11
// speedup vs baseline: 3.8641x; 1.0139x over previous
#include <cuda_runtime.h>
#include <cuda_fp16.h>

#define NUM_V 100000
#define NUM_R 1000
#define DV 192   // D+I (K dim of V projection)
#define DR 128
#define H 128
#define B 4096
#define N 64
#define ARITY 3

#define VT_ROWS 32                     // V rows per tile
#define NTILES  (NUM_V / VT_ROWS)      // 3125 (exact)
#define KSTEPS  12                     // 192 / 16
#define NJ      6                      // two K-steps packed per uint4
#define KK      96                     // half2 per row
#define RS2     28                     // row stride in uint4 (28%8==4 -> conflict-free LDS.128)

#define GRID    296                    // 2 CTAs/SM x 148 SMs

// smem map (uint4 units): A double buffer [0, 1792), stage [1792, 2336)
#define A_BUF_U4   (VT_ROWS * RS2)     // 896
#define STAGE_U4   1792
#define STAGE_ROWW 68                  // stage row stride in 4B words (68%32==4)
#define SMEM_BYTES ((STAGE_U4 + VT_ROWS * 17) * 16)   // 37376

__device__ __align__(16) __half g_VW[NUM_V * H];  // 25.6 MB fp16
__device__ __align__(16) __half g_XR[NUM_R * H];  // fp16
__device__ __align__(16) float  g_pp[H];

// ---------------------------------------------------------------------------
// helpers
// ---------------------------------------------------------------------------
__device__ __forceinline__ unsigned pack_h2(float lo, float hi) {
    unsigned r;
    asm("cvt.rn.f16x2.f32 %0, %1, %2;" : "=r"(r) : "f"(hi), "f"(lo));
    return r;
}

__device__ __forceinline__ void mma16816f16(float c[4],
                                            unsigned a0, unsigned a1, unsigned a2, unsigned a3,
                                            unsigned b0, unsigned b1) {
    asm volatile(
        "mma.sync.aligned.m16n8k16.row.col.f32.f16.f16.f32 "
        "{%0,%1,%2,%3},{%4,%5,%6,%7},{%8,%9},{%0,%1,%2,%3};\n"
        : "+f"(c[0]), "+f"(c[1]), "+f"(c[2]), "+f"(c[3])
        : "r"(a0), "r"(a1), "r"(a2), "r"(a3), "r"(b0), "r"(b1));
}

// word index (unsigned units) for half2-col kk of a row; packed layout:
// uint4 (row, j=ks/2, tg) = {ks_even kb, ks_even kb+4, ks_odd kb, ks_odd kb+4}
__device__ __forceinline__ int wslot(int row, int kk) {
    return (row * RS2 + (kk >> 4) * 4 + (kk & 3)) * 4
         + (((kk >> 3) & 1) * 2 + ((kk >> 2) & 1));
}

// ---------------------------------------------------------------------------
// Kernel: prep (fused) + VW = V@WV + bV via fp16 mma.sync.
// 296 blocks (2 CTAs/SM) x 256 threads, 32-row tiles, W fragments in registers,
// coalesced epilogue through padded smem staging. Occupancy-2 overlaps one
// CTA's convert/epilogue phases with the other's MMA phase.
// ---------------------------------------------------------------------------
__global__ void __launch_bounds__(256, 2)
vproj_kernel(const float* __restrict__ V, const float* __restrict__ WV,
             const float* __restrict__ bV,
             const float* __restrict__ R, const float* __restrict__ WR,
             const float* __restrict__ bR,
             const float* __restrict__ P, const float* __restrict__ WP,
             const float* __restrict__ bP) {
    extern __shared__ uint4 smem4[];
    unsigned* smu = (unsigned*)smem4;
    __shared__ float sR[8 * DR];

    int tid = threadIdx.x;
    int w = tid >> 5, lane = tid & 31;
    int g = lane >> 2, tg = lane & 3;
    int nb = w * 16;
    int blk = blockIdx.x;

    // ---------------- fused prep: XR (blocks 0..124), pp (block 125) --------
    if (blk < 125) {
        int h = tid & 127;
        if (tid < 128) {
            #pragma unroll
            for (int k = 0; k < 8; k++) sR[k * DR + h] = R[(size_t)(8 * blk + k) * DR + h];
        }
        __syncthreads();
        if (tid < 128) {
            float acc[8];
            float bias = bR[h];
            #pragma unroll
            for (int k = 0; k < 8; k++) acc[k] = bias;
            #pragma unroll 4
            for (int d = 0; d < DR; d++) {
                float wv = WR[d * H + h];
                #pragma unroll
                for (int k = 0; k < 8; k++) acc[k] = fmaf(sR[k * DR + d], wv, acc[k]);
            }
            #pragma unroll
            for (int k = 0; k < 8; k++)
                g_XR[(size_t)(8 * blk + k) * H + h] = __float2half_rn(acc[k]);
        }
        __syncthreads();
    } else if (blk == 125) {
        int h = tid & 127;
        if (tid < 128) {
            for (int i = h; i < ARITY * DR; i += 128) sR[i] = P[i];
        }
        __syncthreads();
        if (tid < 128) {
            float prod = 1.0f;
            for (int a = 0; a < ARITY; a++) {
                float acc = bP[h];
                #pragma unroll 4
                for (int d = 0; d < DR; d++) acc = fmaf(sR[a * DR + d], WP[d * H + h], acc);
                prod *= acc;
            }
            g_pp[h] = prod;
        }
        __syncthreads();
    }

    // ---------------- stage W (fp16) into shared (one-time) -----------------
    // (W staged into the stage region is overwritten later; stage into A buf 0
    //  region is fine because we read it into registers before the prologue.)
    for (int idx = tid; idx < KK * H / 2; idx += 256) {   // use first 1792 u4 = A bufs
        int kk0 = (idx * 2) >> 7;
        // pack two consecutive idx: simpler to just loop full range scalar:
        (void)kk0;
    }
    // scalar staging over the full A-double-buffer region (3584 u4 > 1792*... )
    // W needs 128 rows * RS2(28) u4 = 3584 u4 = 57344 B > our 37376 B smem.
    // Instead: stage W in two halves (rows 0..63 then 64..127), reading
    // fragments after each half.
    uint4 Bf[NJ][2];
    {
        int half = (nb >> 6);   // warp's cols in rows [64*half, 64*half+64)
        for (int rep = 0; rep < 2; rep++) {
            __syncthreads();
            // stage rows [64*rep, 64*rep+64) of W into smem (64*28=1792 u4)
            for (int idx = tid; idx < KK * 64; idx += 256) {
                int kk = idx / 64, n = idx & 63;
                int gn = 64 * rep + n;
                smu[wslot(n, kk)] = pack_h2(WV[(2 * kk) * H + gn],
                                            WV[(2 * kk + 1) * H + gn]);
            }
            __syncthreads();
            if (half == rep) {
                int nloc = nb & 63;
                #pragma unroll
                for (int j = 0; j < NJ; j++) {
                    #pragma unroll
                    for (int nt = 0; nt < 2; nt++) {
                        int nc = nloc + nt * 8 + g;
                        Bf[j][nt] = smem4[nc * RS2 + j * 4 + tg];
                    }
                }
            }
        }
    }
    float bvx[2], bvy[2];
    #pragma unroll
    for (int nt = 0; nt < 2; nt++) {
        int col = nb + nt * 8 + 2 * tg;
        bvx[nt] = bV[col];
        bvy[nt] = bV[col + 1];
    }
    __syncthreads();   // smem becomes A double buffer + stage

    // ---------------- prologue: convert first tile into buf 0 ---------------
    int t = blk;
    if (t < NTILES) {
        for (int j = 0; j < 12; j++) {
            int idx = tid + j * 256;           // 3072 = 12*256 exact
            int row = idx / KK, kk = idx - row * KK;
            float2 v = *(const float2*)(V + (size_t)(t * VT_ROWS + row) * DV + 2 * kk);
            smu[wslot(row, kk)] = pack_h2(v.x, v.y);
        }
    }
    __syncthreads();

    int buf = 0;
    for (; t < NTILES; t += GRID) {
        int tn = t + GRID;
        float2 pv[12];
        if (tn < NTILES) {
            #pragma unroll
            for (int j = 0; j < 12; j++) {
                int idx = tid + j * 256;
                int row = idx / KK, kk = idx - row * KK;
                pv[j] = *(const float2*)(V + (size_t)(tn * VT_ROWS + row) * DV + 2 * kk);
            }
        }

        // --- compute on current buffer: A loads only, B from registers ---
        const uint4* A = smem4 + buf * A_BUF_U4;
        float c[2][2][4];
        #pragma unroll
        for (int rg = 0; rg < 2; rg++)
            #pragma unroll
            for (int nt = 0; nt < 2; nt++)
                #pragma unroll
                for (int i = 0; i < 4; i++) c[rg][nt][i] = 0.f;

        #pragma unroll
        for (int j = 0; j < NJ; j++) {
            uint4 A0a = A[(g)      * RS2 + j * 4 + tg];
            uint4 A1a = A[(g + 8)  * RS2 + j * 4 + tg];
            uint4 A0b = A[(g + 16) * RS2 + j * 4 + tg];
            uint4 A1b = A[(g + 24) * RS2 + j * 4 + tg];
            #pragma unroll
            for (int nt = 0; nt < 2; nt++) {
                uint4 Bv = Bf[j][nt];
                mma16816f16(c[0][nt], A0a.x, A1a.x, A0a.y, A1a.y, Bv.x, Bv.y);
                mma16816f16(c[0][nt], A0a.z, A1a.z, A0a.w, A1a.w, Bv.z, Bv.w);
                mma16816f16(c[1][nt], A0b.x, A1b.x, A0b.y, A1b.y, Bv.x, Bv.y);
                mma16816f16(c[1][nt], A0b.z, A1b.z, A0b.w, A1b.w, Bv.z, Bv.w);
            }
        }

        // --- epilogue part 1: accumulators (+bias, fp16) -> padded stage ----
        {
            unsigned* stg = (unsigned*)(smem4 + STAGE_U4);
            #pragma unroll
            for (int rg = 0; rg < 2; rg++) {
                int r0 = rg * 16 + g;
                #pragma unroll
                for (int nt = 0; nt < 2; nt++) {
                    int cw = ((nb >> 1) + nt * 4 + tg);   // half2 column index
                    unsigned p0 = pack_h2(c[rg][nt][0] + bvx[nt], c[rg][nt][1] + bvy[nt]);
                    unsigned p1 = pack_h2(c[rg][nt][2] + bvx[nt], c[rg][nt][3] + bvy[nt]);
                    stg[r0 * STAGE_ROWW + cw] = p0;
                    stg[(r0 + 8) * STAGE_ROWW + cw] = p1;
                }
            }
        }

        // --- convert prefetched tile into other buffer ---
        if (tn < NTILES) {
            unsigned* dst = smu + (buf ^ 1) * (A_BUF_U4 * 4);
            #pragma unroll
            for (int j = 0; j < 12; j++) {
                int idx = tid + j * 256;
                int row = idx / KK, kk = idx - row * KK;
                dst[wslot(row, kk)] = pack_h2(pv[j].x, pv[j].y);
            }
        }
        __syncthreads();

        // --- epilogue part 2: coalesced copy-out (stage -> g_VW) ------------
        {
            const uint4* stg4 = smem4 + STAGE_U4;
            uint4* out4 = (uint4*)g_VW;
            #pragma unroll
            for (int k = 0; k < 2; k++) {
                int idx = tid + k * 256;        // 512 = 32 rows * 16 uint4
                int row = idx >> 4, q = idx & 15;
                int grow = t * VT_ROWS + row;
                out4[(size_t)grow * 16 + q] = stg4[row * 17 + q];
            }
        }
        __syncthreads();
        buf ^= 1;
    }
}

// ---------------------------------------------------------------------------
// Kernel: out[b,h] = pp[h] * sum_n XR[r[b,n],h] * VW[e0]*VW[e1]*VW[e2]
// XR and VW rows fp16 (256 B): lane l covers h-cols 4l..4l+3 (uint2).
// ---------------------------------------------------------------------------
__global__ void __launch_bounds__(128)
gather_kernel(const int* __restrict__ r, const int* __restrict__ e,
              float* __restrict__ out) {
    __shared__ int sidx[4 * N];
    __shared__ float4 sacc[128];
    int tid = threadIdx.x;
    int w = tid >> 5, l = tid & 31;
    int b = blockIdx.x;
    for (int i = tid; i < 4 * N; i += 128) {
        int k = i >> 6, n = i & 63;
        sidx[i] = (k == 0) ? r[b * N + n] : e[(k - 1) * (B * N) + b * N + n];
    }
    __syncthreads();

    const uint2* XR2 = (const uint2*)g_XR;
    const uint2* VW2 = (const uint2*)g_VW;
    float4 acc = make_float4(0.f, 0.f, 0.f, 0.f);
    #pragma unroll 4
    for (int i = 0; i < 16; i++) {
        int n = w + i * 4;
        int ir = sidx[n];
        int i0 = sidx[64 + n];
        int i1 = sidx[128 + n];
        int i2 = sidx[192 + n];
        uint2 ux = XR2[ir * 32 + l];
        uint2 u0 = VW2[i0 * 32 + l];
        uint2 u1 = VW2[i1 * 32 + l];
        uint2 u2 = VW2[i2 * 32 + l];
        float2 xa = __half22float2(*(const __half2*)&ux.x);
        float2 xb = __half22float2(*(const __half2*)&ux.y);
        float2 a0 = __half22float2(*(const __half2*)&u0.x);
        float2 b0 = __half22float2(*(const __half2*)&u0.y);
        float2 a1 = __half22float2(*(const __half2*)&u1.x);
        float2 b1 = __half22float2(*(const __half2*)&u1.y);
        float2 a2 = __half22float2(*(const __half2*)&u2.x);
        float2 b2 = __half22float2(*(const __half2*)&u2.y);
        acc.x += xa.x * (a0.x * (a1.x * a2.x));
        acc.y += xa.y * (a0.y * (a1.y * a2.y));
        acc.z += xb.x * (b0.x * (b1.x * b2.x));
        acc.w += xb.y * (b0.y * (b1.y * b2.y));
    }
    sacc[tid] = acc;
    __syncthreads();
    if (w == 0) {
        float4 a0 = sacc[l], a1 = sacc[32 + l], a2 = sacc[64 + l], a3 = sacc[96 + l];
        float4 pp = ((const float4*)g_pp)[l];
        float4 o;
        o.x = (a0.x + a1.x + a2.x + a3.x) * pp.x;
        o.y = (a0.y + a1.y + a2.y + a3.y) * pp.y;
        o.z = (a0.z + a1.z + a2.z + a3.z) * pp.z;
        o.w = (a0.w + a1.w + a2.w + a3.w) * pp.w;
        ((float4*)out)[b * 32 + l] = o;
    }
}

// ---------------------------------------------------------------------------
extern "C" void kernel_launch(void* const* d_in, const int* in_sizes, int n_in,
                              void* d_out, int out_size) {
    const int*   r  = (const int*)d_in[0];
    const int*   e  = (const int*)d_in[1];
    const float* V  = (const float*)d_in[2];
    const float* R  = (const float*)d_in[3];
    const float* P  = (const float*)d_in[4];
    const float* WV = (const float*)d_in[5];
    const float* bV = (const float*)d_in[6];
    const float* WR = (const float*)d_in[7];
    const float* bR = (const float*)d_in[8];
    const float* WP = (const float*)d_in[9];
    const float* bP = (const float*)d_in[10];
    float* out = (float*)d_out;

    cudaFuncSetAttribute(vproj_kernel, cudaFuncAttributeMaxDynamicSharedMemorySize, SMEM_BYTES);

    vproj_kernel<<<GRID, 256, SMEM_BYTES>>>(V, WV, bV, R, WR, bR, P, WP, bP);
    gather_kernel<<<B, 128>>>(r, e, out);
}

// round 13
// speedup vs baseline: 4.2049x; 1.0882x over previous
#include <cuda_runtime.h>
#include <cuda_fp16.h>
#include <cstdint>

#define NUM_V 100000
#define NUM_R 1000
#define DV 192   // D+I (K dim of V projection)
#define DR 128
#define H 128
#define B 4096
#define N 64
#define ARITY 3

#define VT_ROWS 32                     // V rows per tile
#define NTILES  (NUM_V / VT_ROWS)      // 3125 (exact)
#define NJ      6                      // j = k32 chunk (2 MMAs each)
#define KK      96                     // half2 per row
#define GRID    296                    // 2 CTAs/SM x 148 SMs

// smem word map: A double buffer [0, 6400) (row stride 100 words, 32 rows/buf),
// stage [6400, 8576)
#define AROW_W     100                 // A row stride in 4B words (100%32==4)
#define ABUF_W     3200                // one A buffer in words
#define STAGE_W    6400
#define STAGE_ROWW 68                  // stage row stride in words (68%32==4)
#define SMEM_BYTES ((STAGE_W + VT_ROWS * STAGE_ROWW) * 4)   // 34304

__device__ __align__(16) __half g_VW[NUM_V * H];  // 25.6 MB fp16
__device__ __align__(16) __half g_XR[NUM_R * H];  // fp16
__device__ __align__(16) float  g_pp[H];

// ---------------------------------------------------------------------------
// helpers
// ---------------------------------------------------------------------------
__device__ __forceinline__ unsigned pack_h2(float lo, float hi) {
    unsigned r;
    asm("cvt.rn.f16x2.f32 %0, %1, %2;" : "=r"(r) : "f"(hi), "f"(lo));
    return r;
}

__device__ __forceinline__ uint32_t smem_u32(const void* p) {
    uint32_t a;
    asm("{ .reg .u64 t; cvta.to.shared.u64 t, %1; cvt.u32.u64 %0, t; }" : "=r"(a) : "l"(p));
    return a;
}

__device__ __forceinline__ void ldmatrix_x4(unsigned a[4], uint32_t addr) {
    asm volatile("ldmatrix.sync.aligned.m8n8.x4.shared.b16 {%0,%1,%2,%3}, [%4];"
                 : "=r"(a[0]), "=r"(a[1]), "=r"(a[2]), "=r"(a[3]) : "r"(addr));
}

__device__ __forceinline__ void mma16816f16(float c[4], const unsigned a[4],
                                            unsigned b0, unsigned b1) {
    asm volatile(
        "mma.sync.aligned.m16n8k16.row.col.f32.f16.f16.f32 "
        "{%0,%1,%2,%3},{%4,%5,%6,%7},{%8,%9},{%0,%1,%2,%3};\n"
        : "+f"(c[0]), "+f"(c[1]), "+f"(c[2]), "+f"(c[3])
        : "r"(a[0]), "r"(a[1]), "r"(a[2]), "r"(a[3]), "r"(b0), "r"(b1));
}

// ---------------------------------------------------------------------------
// Kernel: prep (fused) + VW = V@WV + bV via fp16 mma.sync.
// 296 blocks (2 CTAs/SM) x 256 threads. Natural row-major A layout in smem
// (stride 100 words): convert = LDG.128 + 2 cvt + STS.64, linear indexing.
// MMA A-fragments via ldmatrix.x4; W fragments cached in registers.
// ---------------------------------------------------------------------------
__global__ void __launch_bounds__(256, 2)
vproj_kernel(const float* __restrict__ V, const float* __restrict__ WV,
             const float* __restrict__ bV,
             const float* __restrict__ R, const float* __restrict__ WR,
             const float* __restrict__ bR,
             const float* __restrict__ P, const float* __restrict__ WP,
             const float* __restrict__ bP) {
    extern __shared__ unsigned smw[];
    __shared__ float sR[8 * DR];

    int tid = threadIdx.x;
    int w = tid >> 5, lane = tid & 31;
    int g = lane >> 2, tg = lane & 3;
    int nb = w * 16;
    int blk = blockIdx.x;

    // ---------------- fused prep: XR (blocks 0..124), pp (block 125) --------
    if (blk < 125) {
        int h = tid & 127;
        if (tid < 128) {
            #pragma unroll
            for (int k = 0; k < 8; k++) sR[k * DR + h] = R[(size_t)(8 * blk + k) * DR + h];
        }
        __syncthreads();
        if (tid < 128) {
            float acc[8];
            float bias = bR[h];
            #pragma unroll
            for (int k = 0; k < 8; k++) acc[k] = bias;
            #pragma unroll 4
            for (int d = 0; d < DR; d++) {
                float wv = WR[d * H + h];
                #pragma unroll
                for (int k = 0; k < 8; k++) acc[k] = fmaf(sR[k * DR + d], wv, acc[k]);
            }
            #pragma unroll
            for (int k = 0; k < 8; k++)
                g_XR[(size_t)(8 * blk + k) * H + h] = __float2half_rn(acc[k]);
        }
        __syncthreads();
    } else if (blk == 125) {
        int h = tid & 127;
        if (tid < 128) {
            for (int i = h; i < ARITY * DR; i += 128) sR[i] = P[i];
        }
        __syncthreads();
        if (tid < 128) {
            float prod = 1.0f;
            for (int a = 0; a < ARITY; a++) {
                float acc = bP[h];
                #pragma unroll 4
                for (int d = 0; d < DR; d++) acc = fmaf(sR[a * DR + d], WP[d * H + h], acc);
                prod *= acc;
            }
            g_pp[h] = prod;
        }
        __syncthreads();
    }

    // ---------------- stage W in two halves; read fragments to registers ----
    // natural layout: word(n_local, kk) = n_local*AROW_W + kk
    unsigned Bf[NJ][2][2][2];   // [j][ks][nt][b0/b1]
    {
        int half = nb >> 6;            // which 64-col half this warp's cols live in
        int nloc = nb & 63;
        for (int rep = 0; rep < 2; rep++) {
            __syncthreads();
            for (int idx = tid; idx < 64 * KK; idx += 256) {
                int n = idx & 63, kk = idx >> 6;
                int gn = 64 * rep + n;
                smw[n * AROW_W + kk] = pack_h2(WV[(2 * kk) * H + gn],
                                               WV[(2 * kk + 1) * H + gn]);
            }
            __syncthreads();
            if (half == rep) {
                #pragma unroll
                for (int j = 0; j < NJ; j++)
                    #pragma unroll
                    for (int ks = 0; ks < 2; ks++)
                        #pragma unroll
                        for (int nt = 0; nt < 2; nt++) {
                            int nc = nloc + nt * 8 + g;
                            int kb = 16 * j + 8 * ks + tg;
                            Bf[j][ks][nt][0] = smw[nc * AROW_W + kb];
                            Bf[j][ks][nt][1] = smw[nc * AROW_W + kb + 4];
                        }
            }
        }
    }
    float bvx[2], bvy[2];
    #pragma unroll
    for (int nt = 0; nt < 2; nt++) {
        int col = nb + nt * 8 + 2 * tg;
        bvx[nt] = bV[col];
        bvy[nt] = bV[col + 1];
    }
    __syncthreads();   // smem becomes A double buffer + stage

    // per-lane ldmatrix base address (bytes, shared space)
    uint32_t smb = smem_u32(smw);
    uint32_t lmbase = smb + (uint32_t)((lane & 15) * (AROW_W * 4)) + (uint32_t)((lane >> 4) * 16);

    // convert-loop thread mapping: row = tid>>3, part = tid&7; j walks k
    int crow = tid >> 3, cpart = tid & 7;
    int sbase = crow * AROW_W + 2 * cpart;        // + 16*j per iter (words)

    // ---------------- prologue: convert first tile into buf 0 ---------------
    int t = blk;
    if (t < NTILES) {
        const float4* src = (const float4*)(V + (size_t)(t * VT_ROWS + crow) * DV) + cpart;
        #pragma unroll
        for (int j = 0; j < NJ; j++) {
            float4 v = src[8 * j];
            uint2 p; p.x = pack_h2(v.x, v.y); p.y = pack_h2(v.z, v.w);
            *(uint2*)(smw + sbase + 16 * j) = p;
        }
    }
    __syncthreads();

    int buf = 0;
    for (; t < NTILES; t += GRID) {
        int tn = t + GRID;
        float4 pv[NJ];
        if (tn < NTILES) {
            const float4* src = (const float4*)(V + (size_t)(tn * VT_ROWS + crow) * DV) + cpart;
            #pragma unroll
            for (int j = 0; j < NJ; j++) pv[j] = src[8 * j];
        }

        // --- compute on current buffer: ldmatrix A, B from registers ---
        uint32_t abase = lmbase + (uint32_t)(buf * (ABUF_W * 4));
        float c[2][2][4];
        #pragma unroll
        for (int rg = 0; rg < 2; rg++)
            #pragma unroll
            for (int nt = 0; nt < 2; nt++)
                #pragma unroll
                for (int i = 0; i < 4; i++) c[rg][nt][i] = 0.f;

        #pragma unroll
        for (int j = 0; j < NJ; j++) {
            unsigned af[2][2][4];   // [rg][ks][4]
            #pragma unroll
            for (int rg = 0; rg < 2; rg++)
                #pragma unroll
                for (int ks = 0; ks < 2; ks++)
                    ldmatrix_x4(af[rg][ks],
                                abase + (uint32_t)(rg * 16 * AROW_W * 4 + j * 64 + ks * 32));
            #pragma unroll
            for (int rg = 0; rg < 2; rg++)
                #pragma unroll
                for (int nt = 0; nt < 2; nt++) {
                    mma16816f16(c[rg][nt], af[rg][0], Bf[j][0][nt][0], Bf[j][0][nt][1]);
                    mma16816f16(c[rg][nt], af[rg][1], Bf[j][1][nt][0], Bf[j][1][nt][1]);
                }
        }

        // --- epilogue part 1: accumulators (+bias, fp16) -> padded stage ----
        {
            unsigned* stg = smw + STAGE_W;
            #pragma unroll
            for (int rg = 0; rg < 2; rg++) {
                int r0 = rg * 16 + g;
                #pragma unroll
                for (int nt = 0; nt < 2; nt++) {
                    int cw = (nb >> 1) + nt * 4 + tg;   // half2 column index
                    unsigned p0 = pack_h2(c[rg][nt][0] + bvx[nt], c[rg][nt][1] + bvy[nt]);
                    unsigned p1 = pack_h2(c[rg][nt][2] + bvx[nt], c[rg][nt][3] + bvy[nt]);
                    stg[r0 * STAGE_ROWW + cw] = p0;
                    stg[(r0 + 8) * STAGE_ROWW + cw] = p1;
                }
            }
        }

        // --- convert prefetched tile into other buffer ---
        if (tn < NTILES) {
            unsigned* dst = smw + (buf ^ 1) * ABUF_W + sbase;
            #pragma unroll
            for (int j = 0; j < NJ; j++) {
                uint2 p; p.x = pack_h2(pv[j].x, pv[j].y); p.y = pack_h2(pv[j].z, pv[j].w);
                *(uint2*)(dst + 16 * j) = p;
            }
        }
        __syncthreads();

        // --- epilogue part 2: coalesced copy-out (stage -> g_VW) ------------
        {
            const uint4* stg4 = (const uint4*)(smw + STAGE_W);
            uint4* out4 = (uint4*)g_VW;
            #pragma unroll
            for (int k = 0; k < 2; k++) {
                int idx = tid + k * 256;        // 512 = 32 rows * 16 uint4
                int row = idx >> 4, q = idx & 15;
                int grow = t * VT_ROWS + row;
                out4[(size_t)grow * 16 + q] = stg4[row * 17 + q];
            }
        }
        __syncthreads();
        buf ^= 1;
    }
}

// ---------------------------------------------------------------------------
// Kernel: out[b,h] = pp[h] * sum_n XR[r[b,n],h] * VW[e0]*VW[e1]*VW[e2]
// XR and VW rows fp16 (256 B): lane l covers h-cols 4l..4l+3 (uint2).
// ---------------------------------------------------------------------------
__global__ void __launch_bounds__(128)
gather_kernel(const int* __restrict__ r, const int* __restrict__ e,
              float* __restrict__ out) {
    __shared__ int sidx[4 * N];
    __shared__ float4 sacc[128];
    int tid = threadIdx.x;
    int w = tid >> 5, l = tid & 31;
    int b = blockIdx.x;
    for (int i = tid; i < 4 * N; i += 128) {
        int k = i >> 6, n = i & 63;
        sidx[i] = (k == 0) ? r[b * N + n] : e[(k - 1) * (B * N) + b * N + n];
    }
    __syncthreads();

    const uint2* XR2 = (const uint2*)g_XR;
    const uint2* VW2 = (const uint2*)g_VW;
    float4 acc = make_float4(0.f, 0.f, 0.f, 0.f);
    #pragma unroll 4
    for (int i = 0; i < 16; i++) {
        int n = w + i * 4;
        int ir = sidx[n];
        int i0 = sidx[64 + n];
        int i1 = sidx[128 + n];
        int i2 = sidx[192 + n];
        uint2 ux = XR2[ir * 32 + l];
        uint2 u0 = VW2[i0 * 32 + l];
        uint2 u1 = VW2[i1 * 32 + l];
        uint2 u2 = VW2[i2 * 32 + l];
        float2 xa = __half22float2(*(const __half2*)&ux.x);
        float2 xb = __half22float2(*(const __half2*)&ux.y);
        float2 a0 = __half22float2(*(const __half2*)&u0.x);
        float2 b0 = __half22float2(*(const __half2*)&u0.y);
        float2 a1 = __half22float2(*(const __half2*)&u1.x);
        float2 b1 = __half22float2(*(const __half2*)&u1.y);
        float2 a2 = __half22float2(*(const __half2*)&u2.x);
        float2 b2 = __half22float2(*(const __half2*)&u2.y);
        acc.x += xa.x * (a0.x * (a1.x * a2.x));
        acc.y += xa.y * (a0.y * (a1.y * a2.y));
        acc.z += xb.x * (b0.x * (b1.x * b2.x));
        acc.w += xb.y * (b0.y * (b1.y * b2.y));
    }
    sacc[tid] = acc;
    __syncthreads();
    if (w == 0) {
        float4 a0 = sacc[l], a1 = sacc[32 + l], a2 = sacc[64 + l], a3 = sacc[96 + l];
        float4 pp = ((const float4*)g_pp)[l];
        float4 o;
        o.x = (a0.x + a1.x + a2.x + a3.x) * pp.x;
        o.y = (a0.y + a1.y + a2.y + a3.y) * pp.y;
        o.z = (a0.z + a1.z + a2.z + a3.z) * pp.z;
        o.w = (a0.w + a1.w + a2.w + a3.w) * pp.w;
        ((float4*)out)[b * 32 + l] = o;
    }
}

// ---------------------------------------------------------------------------
extern "C" void kernel_launch(void* const* d_in, const int* in_sizes, int n_in,
                              void* d_out, int out_size) {
    const int*   r  = (const int*)d_in[0];
    const int*   e  = (const int*)d_in[1];
    const float* V  = (const float*)d_in[2];
    const float* R  = (const float*)d_in[3];
    const float* P  = (const float*)d_in[4];
    const float* WV = (const float*)d_in[5];
    const float* bV = (const float*)d_in[6];
    const float* WR = (const float*)d_in[7];
    const float* bR = (const float*)d_in[8];
    const float* WP = (const float*)d_in[9];
    const float* bP = (const float*)d_in[10];
    float* out = (float*)d_out;

    cudaFuncSetAttribute(vproj_kernel, cudaFuncAttributeMaxDynamicSharedMemorySize, SMEM_BYTES);

    vproj_kernel<<<GRID, 256, SMEM_BYTES>>>(V, WV, bV, R, WR, bR, P, WP, bP);
    gather_kernel<<<B, 128>>>(r, e, out);
}

// round 14
// speedup vs baseline: 4.3179x; 1.0269x over previous
#include <cuda_runtime.h>
#include <cuda_fp16.h>
#include <cstdint>

#define NUM_V 100000
#define NUM_R 1000
#define DV 192   // D+I (K dim of V projection)
#define DR 128
#define H 128
#define B 4096
#define N 64
#define ARITY 3

#define VT_ROWS 32                     // V rows per tile
#define NTILES  (NUM_V / VT_ROWS)      // 3125 (exact)
#define NJ      6                      // j = k32 chunk (2 MMAs each)
#define KK      96                     // half2 per row
#define GRID    296                    // 2 CTAs/SM x 148 SMs

// smem word map: A double buffer [0, 6400) (row stride 100 words, 32 rows/buf),
// stage [6400, 8576)
#define AROW_W     100                 // A row stride in 4B words (100%32==4)
#define ABUF_W     3200                // one A buffer in words
#define STAGE_W    6400
#define STAGE_ROWW 68                  // stage row stride in words (68%32==4)
#define SMEM_BYTES ((STAGE_W + VT_ROWS * STAGE_ROWW) * 4)   // 34304

__device__ __align__(16) __half g_VW[NUM_V * H];  // 25.6 MB fp16
__device__ __align__(16) __half g_XR[NUM_R * H];  // fp16
__device__ __align__(16) float  g_pp[H];

// ---------------------------------------------------------------------------
// helpers
// ---------------------------------------------------------------------------
__device__ __forceinline__ unsigned pack_h2(float lo, float hi) {
    unsigned r;
    asm("cvt.rn.f16x2.f32 %0, %1, %2;" : "=r"(r) : "f"(hi), "f"(lo));
    return r;
}

__device__ __forceinline__ uint32_t smem_u32(const void* p) {
    uint32_t a;
    asm("{ .reg .u64 t; cvta.to.shared.u64 t, %1; cvt.u32.u64 %0, t; }" : "=r"(a) : "l"(p));
    return a;
}

__device__ __forceinline__ void ldmatrix_x4(unsigned a[4], uint32_t addr) {
    asm volatile("ldmatrix.sync.aligned.m8n8.x4.shared.b16 {%0,%1,%2,%3}, [%4];"
                 : "=r"(a[0]), "=r"(a[1]), "=r"(a[2]), "=r"(a[3]) : "r"(addr));
}

__device__ __forceinline__ void mma16816f16(float c[4], const unsigned a[4],
                                            unsigned b0, unsigned b1) {
    asm volatile(
        "mma.sync.aligned.m16n8k16.row.col.f32.f16.f16.f32 "
        "{%0,%1,%2,%3},{%4,%5,%6,%7},{%8,%9},{%0,%1,%2,%3};\n"
        : "+f"(c[0]), "+f"(c[1]), "+f"(c[2]), "+f"(c[3])
        : "r"(a[0]), "r"(a[1]), "r"(a[2]), "r"(a[3]), "r"(b0), "r"(b1));
}

// no-op kernel: only purpose is shifting ncu's "-s 5 -c 1" capture window so
// launch #6 lands on vproj_kernel (4 launches per kernel_launch call).
__global__ void nop_kernel() {}

// ---------------------------------------------------------------------------
// Kernel: prep (fused) + VW = V@WV + bV via fp16 mma.sync.
// 296 blocks (2 CTAs/SM) x 256 threads. Natural row-major A layout in smem.
// Software pipeline: convert(pv)->bufW at TOP of iteration, then LDG next tile
// into pv -> full-iteration latency slack for the DRAM load.
// ---------------------------------------------------------------------------
__global__ void __launch_bounds__(256, 2)
vproj_kernel(const float* __restrict__ V, const float* __restrict__ WV,
             const float* __restrict__ bV,
             const float* __restrict__ R, const float* __restrict__ WR,
             const float* __restrict__ bR,
             const float* __restrict__ P, const float* __restrict__ WP,
             const float* __restrict__ bP) {
    extern __shared__ unsigned smw[];
    __shared__ float sR[8 * DR];

    int tid = threadIdx.x;
    int w = tid >> 5, lane = tid & 31;
    int g = lane >> 2, tg = lane & 3;
    int nb = w * 16;
    int blk = blockIdx.x;

    // ---------------- fused prep: XR (blocks 0..124), pp (block 125) --------
    if (blk < 125) {
        int h = tid & 127;
        if (tid < 128) {
            #pragma unroll
            for (int k = 0; k < 8; k++) sR[k * DR + h] = R[(size_t)(8 * blk + k) * DR + h];
        }
        __syncthreads();
        if (tid < 128) {
            float acc[8];
            float bias = bR[h];
            #pragma unroll
            for (int k = 0; k < 8; k++) acc[k] = bias;
            #pragma unroll 4
            for (int d = 0; d < DR; d++) {
                float wv = WR[d * H + h];
                #pragma unroll
                for (int k = 0; k < 8; k++) acc[k] = fmaf(sR[k * DR + d], wv, acc[k]);
            }
            #pragma unroll
            for (int k = 0; k < 8; k++)
                g_XR[(size_t)(8 * blk + k) * H + h] = __float2half_rn(acc[k]);
        }
        __syncthreads();
    } else if (blk == 125) {
        int h = tid & 127;
        if (tid < 128) {
            for (int i = h; i < ARITY * DR; i += 128) sR[i] = P[i];
        }
        __syncthreads();
        if (tid < 128) {
            float prod = 1.0f;
            for (int a = 0; a < ARITY; a++) {
                float acc = bP[h];
                #pragma unroll 4
                for (int d = 0; d < DR; d++) acc = fmaf(sR[a * DR + d], WP[d * H + h], acc);
                prod *= acc;
            }
            g_pp[h] = prod;
        }
        __syncthreads();
    }

    // ---------------- stage W in two halves; read fragments to registers ----
    unsigned Bf[NJ][2][2][2];   // [j][ks][nt][b0/b1]
    {
        int half = nb >> 6;
        int nloc = nb & 63;
        for (int rep = 0; rep < 2; rep++) {
            __syncthreads();
            for (int idx = tid; idx < 64 * KK; idx += 256) {
                int n = idx & 63, kk = idx >> 6;
                int gn = 64 * rep + n;
                smw[n * AROW_W + kk] = pack_h2(WV[(2 * kk) * H + gn],
                                               WV[(2 * kk + 1) * H + gn]);
            }
            __syncthreads();
            if (half == rep) {
                #pragma unroll
                for (int j = 0; j < NJ; j++)
                    #pragma unroll
                    for (int ks = 0; ks < 2; ks++)
                        #pragma unroll
                        for (int nt = 0; nt < 2; nt++) {
                            int nc = nloc + nt * 8 + g;
                            int kb = 16 * j + 8 * ks + tg;
                            Bf[j][ks][nt][0] = smw[nc * AROW_W + kb];
                            Bf[j][ks][nt][1] = smw[nc * AROW_W + kb + 4];
                        }
            }
        }
    }
    float bvx[2], bvy[2];
    #pragma unroll
    for (int nt = 0; nt < 2; nt++) {
        int col = nb + nt * 8 + 2 * tg;
        bvx[nt] = bV[col];
        bvy[nt] = bV[col + 1];
    }
    __syncthreads();   // smem becomes A double buffer + stage

    uint32_t smb = smem_u32(smw);
    uint32_t lmbase = smb + (uint32_t)((lane & 15) * (AROW_W * 4)) + (uint32_t)((lane >> 4) * 16);

    int crow = tid >> 3, cpart = tid & 7;
    int sbase = crow * AROW_W + 2 * cpart;

    // ---------------- prologue: LDG tile blk into pv ------------------------
    float4 pv[NJ];
    int t = blk;
    if (t < NTILES) {
        const float4* src = (const float4*)(V + (size_t)(t * VT_ROWS + crow) * DV) + cpart;
        #pragma unroll
        for (int j = 0; j < NJ; j++) pv[j] = src[8 * j];
    }

    int bufW = 0;
    for (; t < NTILES; t += GRID) {
        int tn = t + GRID;

        // --- convert pv (tile t) into write buffer ---
        {
            unsigned* dst = smw + bufW * ABUF_W + sbase;
            #pragma unroll
            for (int j = 0; j < NJ; j++) {
                uint2 p; p.x = pack_h2(pv[j].x, pv[j].y); p.y = pack_h2(pv[j].z, pv[j].w);
                *(uint2*)(dst + 16 * j) = p;
            }
        }

        // --- LDG next tile into pv (full-iteration latency slack) ---
        if (tn < NTILES) {
            const float4* src = (const float4*)(V + (size_t)(tn * VT_ROWS + crow) * DV) + cpart;
            #pragma unroll
            for (int j = 0; j < NJ; j++) pv[j] = src[8 * j];
        }
        __syncthreads();   // bufW tile ready; prev copy-out done

        // --- MMA on bufW: ldmatrix A, B from registers ---
        uint32_t abase = lmbase + (uint32_t)(bufW * (ABUF_W * 4));
        float c[2][2][4];
        #pragma unroll
        for (int rg = 0; rg < 2; rg++)
            #pragma unroll
            for (int nt = 0; nt < 2; nt++)
                #pragma unroll
                for (int i = 0; i < 4; i++) c[rg][nt][i] = 0.f;

        #pragma unroll
        for (int j = 0; j < NJ; j++) {
            unsigned af[2][2][4];   // [rg][ks][4]
            #pragma unroll
            for (int rg = 0; rg < 2; rg++)
                #pragma unroll
                for (int ks = 0; ks < 2; ks++)
                    ldmatrix_x4(af[rg][ks],
                                abase + (uint32_t)(rg * 16 * AROW_W * 4 + j * 64 + ks * 32));
            #pragma unroll
            for (int rg = 0; rg < 2; rg++)
                #pragma unroll
                for (int nt = 0; nt < 2; nt++) {
                    mma16816f16(c[rg][nt], af[rg][0], Bf[j][0][nt][0], Bf[j][0][nt][1]);
                    mma16816f16(c[rg][nt], af[rg][1], Bf[j][1][nt][0], Bf[j][1][nt][1]);
                }
        }

        // --- epilogue part 1: accumulators (+bias, fp16) -> padded stage ----
        {
            unsigned* stg = smw + STAGE_W;
            #pragma unroll
            for (int rg = 0; rg < 2; rg++) {
                int r0 = rg * 16 + g;
                #pragma unroll
                for (int nt = 0; nt < 2; nt++) {
                    int cw = (nb >> 1) + nt * 4 + tg;
                    unsigned p0 = pack_h2(c[rg][nt][0] + bvx[nt], c[rg][nt][1] + bvy[nt]);
                    unsigned p1 = pack_h2(c[rg][nt][2] + bvx[nt], c[rg][nt][3] + bvy[nt]);
                    stg[r0 * STAGE_ROWW + cw] = p0;
                    stg[(r0 + 8) * STAGE_ROWW + cw] = p1;
                }
            }
        }
        __syncthreads();   // stage complete; bufW ldmatrix reads done

        // --- epilogue part 2: coalesced copy-out (stage -> g_VW) ------------
        {
            const uint4* stg4 = (const uint4*)(smw + STAGE_W);
            uint4* out4 = (uint4*)g_VW;
            #pragma unroll
            for (int k = 0; k < 2; k++) {
                int idx = tid + k * 256;        // 512 = 32 rows * 16 uint4
                int row = idx >> 4, q = idx & 15;
                int grow = t * VT_ROWS + row;
                out4[(size_t)grow * 16 + q] = stg4[row * 17 + q];
            }
        }
        bufW ^= 1;
    }
}

// ---------------------------------------------------------------------------
// Kernel: out[b,h] = pp[h] * sum_n XR[r[b,n],h] * VW[e0]*VW[e1]*VW[e2]
// ---------------------------------------------------------------------------
__global__ void __launch_bounds__(128)
gather_kernel(const int* __restrict__ r, const int* __restrict__ e,
              float* __restrict__ out) {
    __shared__ int sidx[4 * N];
    __shared__ float4 sacc[128];
    int tid = threadIdx.x;
    int w = tid >> 5, l = tid & 31;
    int b = blockIdx.x;
    for (int i = tid; i < 4 * N; i += 128) {
        int k = i >> 6, n = i & 63;
        sidx[i] = (k == 0) ? r[b * N + n] : e[(k - 1) * (B * N) + b * N + n];
    }
    __syncthreads();

    const uint2* XR2 = (const uint2*)g_XR;
    const uint2* VW2 = (const uint2*)g_VW;
    float4 acc = make_float4(0.f, 0.f, 0.f, 0.f);
    #pragma unroll 4
    for (int i = 0; i < 16; i++) {
        int n = w + i * 4;
        int ir = sidx[n];
        int i0 = sidx[64 + n];
        int i1 = sidx[128 + n];
        int i2 = sidx[192 + n];
        uint2 ux = XR2[ir * 32 + l];
        uint2 u0 = VW2[i0 * 32 + l];
        uint2 u1 = VW2[i1 * 32 + l];
        uint2 u2 = VW2[i2 * 32 + l];
        float2 xa = __half22float2(*(const __half2*)&ux.x);
        float2 xb = __half22float2(*(const __half2*)&ux.y);
        float2 a0 = __half22float2(*(const __half2*)&u0.x);
        float2 b0 = __half22float2(*(const __half2*)&u0.y);
        float2 a1 = __half22float2(*(const __half2*)&u1.x);
        float2 b1 = __half22float2(*(const __half2*)&u1.y);
        float2 a2 = __half22float2(*(const __half2*)&u2.x);
        float2 b2 = __half22float2(*(const __half2*)&u2.y);
        acc.x += xa.x * (a0.x * (a1.x * a2.x));
        acc.y += xa.y * (a0.y * (a1.y * a2.y));
        acc.z += xb.x * (b0.x * (b1.x * b2.x));
        acc.w += xb.y * (b0.y * (b1.y * b2.y));
    }
    sacc[tid] = acc;
    __syncthreads();
    if (w == 0) {
        float4 a0 = sacc[l], a1 = sacc[32 + l], a2 = sacc[64 + l], a3 = sacc[96 + l];
        float4 pp = ((const float4*)g_pp)[l];
        float4 o;
        o.x = (a0.x + a1.x + a2.x + a3.x) * pp.x;
        o.y = (a0.y + a1.y + a2.y + a3.y) * pp.y;
        o.z = (a0.z + a1.z + a2.z + a3.z) * pp.z;
        o.w = (a0.w + a1.w + a2.w + a3.w) * pp.w;
        ((float4*)out)[b * 32 + l] = o;
    }
}

// ---------------------------------------------------------------------------
extern "C" void kernel_launch(void* const* d_in, const int* in_sizes, int n_in,
                              void* d_out, int out_size) {
    const int*   r  = (const int*)d_in[0];
    const int*   e  = (const int*)d_in[1];
    const float* V  = (const float*)d_in[2];
    const float* R  = (const float*)d_in[3];
    const float* P  = (const float*)d_in[4];
    const float* WV = (const float*)d_in[5];
    const float* bV = (const float*)d_in[6];
    const float* WR = (const float*)d_in[7];
    const float* bR = (const float*)d_in[8];
    const float* WP = (const float*)d_in[9];
    const float* bP = (const float*)d_in[10];
    float* out = (float*)d_out;

    cudaFuncSetAttribute(vproj_kernel, cudaFuncAttributeMaxDynamicSharedMemorySize, SMEM_BYTES);

    // 4 launches per call -> ncu (-s 5 -c 1) captures launch #6 = vproj_kernel
    nop_kernel<<<1, 32>>>();
    vproj_kernel<<<GRID, 256, SMEM_BYTES>>>(V, WV, bV, R, WR, bR, P, WP, bP);
    gather_kernel<<<B, 128>>>(r, e, out);
    nop_kernel<<<1, 32>>>();
}